// round 1
// baseline (speedup 1.0000x reference)
#include <cuda_runtime.h>
#include <math.h>

#define B_  32
#define H_  56
#define W_  56
#define C_  192
#define D_  64
#define M_  8
#define HW_ 3136
#define N_  (B_*HW_)

// ---------------- device scratch (no allocations allowed) ----------------
__device__ float g_pf[(size_t)N_ * 64];          // [n][64]
__device__ float g_xp[(size_t)B_ * D_ * HW_];    // [b][d][hw]  (gelu'd down-proj)
__device__ float g_logits[(size_t)M_ * B_ * HW_];// [m][b][hw]
__device__ float g_stats[M_ * B_ * 2];           // per (m,b): max, 1/sum
__device__ float g_mwf[B_ * D_];                 // [b][64]
__device__ float g_convw[(size_t)B_ * D_ * D_ * 9]; // [b][oc][ic][3][3]

__device__ __forceinline__ float qgelu(float v) {
    return v / (1.f + expf(-1.702f * v));
}

// ============================================================================
// K1: fused  h = relu(x@W1^T + b1);  xp = qgelu(x@Wd^T + bd) (transposed);
//            pf = h@W2^T + b2;       logits[m] = pf . mask_token[m]
// block: 128 positions x 128 outputs (64 h || 64 xd), 256 threads, 8x8 regs
// ============================================================================
__global__ __launch_bounds__(256) void k1(
    const float* __restrict__ x, const float* __restrict__ W1, const float* __restrict__ b1,
    const float* __restrict__ W2, const float* __restrict__ b2, const float* __restrict__ mtok,
    const float* __restrict__ Wd, const float* __restrict__ bd)
{
    extern __shared__ float sm[];
    float* As = sm;              // 16*132 = 2112
    float* Bs = sm + 2112;       // 16*132 = 2112
    float* hs = sm + 4224;       // 128*66 = 8448 (h, then pf)
    __shared__ float mt_s[M_ * 64];

    const int tid = threadIdx.x;
    const int b   = blockIdx.y;
    const int hw0 = blockIdx.x * 128;
    const int P   = min(128, HW_ - hw0);
    const int tx  = tid & 15;   // output index base
    const int ty  = tid >> 4;   // position index base

    for (int i = tid; i < M_ * 64; i += 256) mt_s[i] = mtok[i];

    float c1[8][8];
    #pragma unroll
    for (int i = 0; i < 8; i++)
        #pragma unroll
        for (int j = 0; j < 8; j++) c1[i][j] = 0.f;

    const float* xb = x + (size_t)(b * HW_ + hw0) * C_;

    for (int k0 = 0; k0 < C_; k0 += 16) {
        __syncthreads();
        // stage x tile: As[k][pos]
        for (int i = tid; i < 2048; i += 256) {
            int p = i >> 4, kk = i & 15;
            As[kk * 132 + p] = (p < P) ? xb[(size_t)p * C_ + k0 + kk] : 0.f;
        }
        // stage combined weights: Bs[k][o]  (o<64: W1 row o ; o>=64: Wd row o-64)
        for (int i = tid; i < 2048; i += 256) {
            int o = i >> 4, kk = i & 15;
            float v = (o < 64) ? W1[o * C_ + k0 + kk] : Wd[(o - 64) * C_ + k0 + kk];
            Bs[kk * 132 + o] = v;
        }
        __syncthreads();
        #pragma unroll
        for (int kk = 0; kk < 16; kk++) {
            float a[8], bb[8];
            #pragma unroll
            for (int i = 0; i < 8; i++) a[i]  = As[kk * 132 + ty + 16 * i];
            #pragma unroll
            for (int j = 0; j < 8; j++) bb[j] = Bs[kk * 132 + tx + 16 * j];
            #pragma unroll
            for (int i = 0; i < 8; i++)
                #pragma unroll
                for (int j = 0; j < 8; j++) c1[i][j] = fmaf(a[i], bb[j], c1[i][j]);
        }
    }
    __syncthreads();

    // epilogue: relu -> hs ; qgelu -> g_xp (transposed)
    #pragma unroll
    for (int j = 0; j < 8; j++) {
        int o = tx + 16 * j;
        if (o < 64) {
            float bias = b1[o];
            #pragma unroll
            for (int i = 0; i < 8; i++) {
                int p = ty + 16 * i;
                hs[p * 66 + o] = fmaxf(c1[i][j] + bias, 0.f);
            }
        } else {
            int d = o - 64;
            float bias = bd[d];
            float* xpd = g_xp + (size_t)(b * D_ + d) * HW_ + hw0;
            #pragma unroll
            for (int i = 0; i < 8; i++) {
                int p = ty + 16 * i;
                if (p < P) xpd[p] = qgelu(c1[i][j] + bias);
            }
        }
    }

    // stage W2 (64x64) into As+Bs region: W2s[k*66 + o]
    float* W2s = sm;
    for (int i = tid; i < 4096; i += 256) {
        int o = i >> 6, kk = i & 63;
        W2s[kk * 66 + o] = W2[o * 64 + kk];
    }
    __syncthreads();

    // pf = h @ W2^T : 128 pos x 64 out, thread tile 8x4
    float c2[8][4];
    #pragma unroll
    for (int i = 0; i < 8; i++)
        #pragma unroll
        for (int j = 0; j < 4; j++) c2[i][j] = 0.f;
    #pragma unroll 4
    for (int kk = 0; kk < 64; kk++) {
        float a[8], bb[4];
        #pragma unroll
        for (int i = 0; i < 8; i++) a[i]  = hs[(ty + 16 * i) * 66 + kk];
        #pragma unroll
        for (int j = 0; j < 4; j++) bb[j] = W2s[kk * 66 + tx + 16 * j];
        #pragma unroll
        for (int i = 0; i < 8; i++)
            #pragma unroll
            for (int j = 0; j < 4; j++) c2[i][j] = fmaf(a[i], bb[j], c2[i][j]);
    }
    __syncthreads();

    // write pf to smem (overwrite hs) and global
    #pragma unroll
    for (int j = 0; j < 4; j++) {
        int o = tx + 16 * j;
        float bias = b2[o];
        #pragma unroll
        for (int i = 0; i < 8; i++) {
            int p = ty + 16 * i;
            float v = c2[i][j] + bias;
            hs[p * 66 + o] = v;
            if (p < P) g_pf[(size_t)(b * HW_ + hw0 + p) * 64 + o] = v;
        }
    }
    __syncthreads();

    // logits: 128 pos x 8 masks
    #pragma unroll
    for (int q = 0; q < 4; q++) {
        int t = tid + 256 * q;
        int p = t & 127, m = t >> 7;
        float acc = 0.f;
        #pragma unroll 8
        for (int k = 0; k < 64; k++) acc = fmaf(hs[p * 66 + k], mt_s[m * 64 + k], acc);
        if (p < P) g_logits[(size_t)(m * B_ + b) * HW_ + hw0 + p] = acc;
    }
}

// ============================================================================
// K2: per-(m,b) softmax stats over 3136 positions
// ============================================================================
__global__ __launch_bounds__(128) void k2()
{
    int row = blockIdx.x;
    const float* l = g_logits + (size_t)row * HW_;
    __shared__ float red[128];
    int tid = threadIdx.x;

    float mx = -3.4e38f;
    for (int p = tid; p < HW_; p += 128) mx = fmaxf(mx, l[p]);
    red[tid] = mx; __syncthreads();
    for (int s = 64; s > 0; s >>= 1) {
        if (tid < s) red[tid] = fmaxf(red[tid], red[tid + s]);
        __syncthreads();
    }
    mx = red[0]; __syncthreads();

    float sum = 0.f;
    for (int p = tid; p < HW_; p += 128) sum += expf(l[p] - mx);
    red[tid] = sum; __syncthreads();
    for (int s = 64; s > 0; s >>= 1) {
        if (tid < s) red[tid] += red[tid + s];
        __syncthreads();
    }
    if (tid == 0) { g_stats[row * 2] = mx; g_stats[row * 2 + 1] = 1.f / red[0]; }
}

// ============================================================================
// K3: masksum[b,p] = sum_m softmax ; mwf[b,k] = sum_p masksum * pf
// ============================================================================
__global__ __launch_bounds__(256) void k3()
{
    int b = blockIdx.x, tid = threadIdx.x;
    __shared__ float ms[HW_];
    __shared__ float mxs[M_], izs[M_];
    __shared__ float red[4][64];

    if (tid < M_) {
        mxs[tid] = g_stats[(tid * B_ + b) * 2];
        izs[tid] = g_stats[(tid * B_ + b) * 2 + 1];
    }
    __syncthreads();

    for (int p = tid; p < HW_; p += 256) {
        float s = 0.f;
        #pragma unroll
        for (int m = 0; m < M_; m++)
            s += expf(g_logits[(size_t)(m * B_ + b) * HW_ + p] - mxs[m]) * izs[m];
        ms[p] = s;
    }
    __syncthreads();

    int k = tid & 63, g = tid >> 6;
    float acc = 0.f;
    const float* pfb = g_pf + (size_t)b * HW_ * 64;
    for (int p = g; p < HW_; p += 4)
        acc = fmaf(ms[p], pfb[(size_t)p * 64 + k], acc);
    red[g][k] = acc;
    __syncthreads();
    if (g == 0) g_mwf[b * 64 + k] = red[0][k] + red[1][k] + red[2][k] + red[3][k];
}

// ============================================================================
// K4: conv_w[b,o] = mwf[b] . Wh[o] + bh[o]   (o = 36864, 144 blocks x 256 o)
// ============================================================================
__global__ __launch_bounds__(256) void k4(const float* __restrict__ Wh,
                                          const float* __restrict__ bh)
{
    extern __shared__ float sm[];
    float* whs = sm;              // 256*65
    float* mw  = sm + 256 * 65;   // 32*64
    int tid = threadIdx.x;
    int o0 = blockIdx.x * 256;

    for (int i = tid; i < 2048; i += 256) mw[i] = g_mwf[i];
    for (int i = tid; i < 256 * 64; i += 256) {
        int ol = i >> 6, kk = i & 63;
        whs[ol * 65 + kk] = Wh[(size_t)(o0 + ol) * 64 + kk];
    }
    __syncthreads();

    int o = o0 + tid;
    float bias = bh[o];
    const float* wr = whs + tid * 65;
    for (int b = 0; b < B_; b++) {
        float acc = bias;
        const float* mb = mw + b * 64;
        #pragma unroll 16
        for (int kk = 0; kk < 64; kk++) acc = fmaf(mb[kk], wr[kk], acc);
        g_convw[(size_t)b * 36864 + o] = acc;
    }
}

// ============================================================================
// K5: per-sample 3x3 conv (64->64) + quickGELU + up-proj + residual, fused.
// grid (49 tiles of 8x8, 32 b), 256 threads, ~222KB smem, 1 block/SM.
// ============================================================================
__global__ __launch_bounds__(256, 1) void k5(const float* __restrict__ x,
                                             const float* __restrict__ Wu,
                                             const float* __restrict__ bu,
                                             float* __restrict__ out)
{
    extern __shared__ float sm[];
    float* cw  = sm;                   // 36864  conv weights [oc][ic][9]
    float* buf = sm + 36864;           // 6400   halo input / later gelu buf [64][65]
    float* wu  = sm + 36864 + 6400;    // 64*193 Wu transposed [d][c] padded

    int tid = threadIdx.x;
    int b = blockIdx.y;
    int t = blockIdx.x;
    int y0 = (t / 7) * 8, x0 = (t % 7) * 8;

    {   // conv weights, vectorized
        const float4* src = (const float4*)(g_convw + (size_t)b * 36864);
        float4* dst = (float4*)cw;
        for (int i = tid; i < 9216; i += 256) dst[i] = src[i];
    }
    // Wu transposed into smem: wu[d*193 + c]
    for (int i = tid; i < 12288; i += 256) {
        int c = i >> 6, d = i & 63;
        wu[d * 193 + c] = Wu[i];
    }
    // halo input tile [64][10][10], zero-padded at borders
    for (int i = tid; i < 6400; i += 256) {
        int d = i / 100, r = (i % 100) / 10, cc = i % 10;
        int gy = y0 - 1 + r, gx = x0 - 1 + cc;
        float v = 0.f;
        if (gy >= 0 && gy < H_ && gx >= 0 && gx < W_)
            v = g_xp[(size_t)(b * D_ + d) * HW_ + gy * W_ + gx];
        buf[i] = v;
    }
    __syncthreads();

    // conv: thread = 4 positions x 4 out-channels
    int og = tid >> 4, pg = tid & 15;
    int oc0 = og * 4;
    int pbase[4];
    #pragma unroll
    for (int i = 0; i < 4; i++) {
        int p = pg * 4 + i;
        pbase[i] = (p >> 3) * 10 + (p & 7);
    }
    float acc[16];
    #pragma unroll
    for (int i = 0; i < 16; i++) acc[i] = 0.f;
    const int offs[9] = {0, 1, 2, 10, 11, 12, 20, 21, 22};

    for (int d = 0; d < 64; d++) {
        const float* ind = buf + d * 100;
        const float* cwd = cw + oc0 * 576 + d * 9;
        #pragma unroll
        for (int tap = 0; tap < 9; tap++) {
            float w0 = cwd[tap], w1 = cwd[576 + tap], w2 = cwd[1152 + tap], w3 = cwd[1728 + tap];
            #pragma unroll
            for (int i = 0; i < 4; i++) {
                float xv = ind[pbase[i] + offs[tap]];
                acc[i * 4 + 0] = fmaf(xv, w0, acc[i * 4 + 0]);
                acc[i * 4 + 1] = fmaf(xv, w1, acc[i * 4 + 1]);
                acc[i * 4 + 2] = fmaf(xv, w2, acc[i * 4 + 2]);
                acc[i * 4 + 3] = fmaf(xv, w3, acc[i * 4 + 3]);
            }
        }
    }
    __syncthreads();   // everyone done reading halo input

    // quickGELU -> buf as g[pos][d] padded 65
    #pragma unroll
    for (int i = 0; i < 4; i++) {
        int p = pg * 4 + i;
        #pragma unroll
        for (int j = 0; j < 4; j++) buf[p * 65 + oc0 + j] = qgelu(acc[i * 4 + j]);
    }
    __syncthreads();

    // up-proj + residual: warp w owns positions w*8..w*8+7; lane owns 6 channels
    int wid = tid >> 5, lane = tid & 31;
    for (int pp = 0; pp < 8; pp++) {
        int p = wid * 8 + pp;
        int gy = y0 + (p >> 3), gx = x0 + (p & 7);
        size_t n = (size_t)b * HW_ + gy * W_ + gx;
        const float* xr = x + n * C_;
        float* orr = out + n * C_;
        float a0 = bu[lane      ] + xr[lane      ];
        float a1 = bu[lane + 32 ] + xr[lane + 32 ];
        float a2 = bu[lane + 64 ] + xr[lane + 64 ];
        float a3 = bu[lane + 96 ] + xr[lane + 96 ];
        float a4 = bu[lane + 128] + xr[lane + 128];
        float a5 = bu[lane + 160] + xr[lane + 160];
        const float* gp = buf + p * 65;
        #pragma unroll 4
        for (int d = 0; d < 64; d++) {
            float gv = gp[d];
            const float* wr = wu + d * 193 + lane;
            a0 = fmaf(gv, wr[0],   a0);
            a1 = fmaf(gv, wr[32],  a1);
            a2 = fmaf(gv, wr[64],  a2);
            a3 = fmaf(gv, wr[96],  a3);
            a4 = fmaf(gv, wr[128], a4);
            a5 = fmaf(gv, wr[160], a5);
        }
        orr[lane      ] = a0;
        orr[lane + 32 ] = a1;
        orr[lane + 64 ] = a2;
        orr[lane + 96 ] = a3;
        orr[lane + 128] = a4;
        orr[lane + 160] = a5;
    }
}

// ============================================================================
extern "C" void kernel_launch(void* const* d_in, const int* in_sizes, int n_in,
                              void* d_out, int out_size)
{
    const float* x  = (const float*)d_in[0];
    const float* W1 = (const float*)d_in[1];
    const float* b1 = (const float*)d_in[2];
    const float* W2 = (const float*)d_in[3];
    const float* b2 = (const float*)d_in[4];
    const float* mt = (const float*)d_in[5];
    const float* Wh = (const float*)d_in[6];
    const float* bh = (const float*)d_in[7];
    const float* Wd = (const float*)d_in[8];
    const float* bd = (const float*)d_in[9];
    const float* Wu = (const float*)d_in[10];
    const float* bu = (const float*)d_in[11];
    float* out = (float*)d_out;

    cudaFuncSetAttribute(k1, cudaFuncAttributeMaxDynamicSharedMemorySize, 50688);
    cudaFuncSetAttribute(k4, cudaFuncAttributeMaxDynamicSharedMemorySize, 74752);
    cudaFuncSetAttribute(k5, cudaFuncAttributeMaxDynamicSharedMemorySize, 222464);

    k1<<<dim3(25, 32), 256, 50688>>>(x, W1, b1, W2, b2, mt, Wd, bd);
    k2<<<256, 128>>>();
    k3<<<32, 256>>>();
    k4<<<144, 256, 74752>>>(Wh, bh);
    k5<<<dim3(49, 32), 256, 222464>>>(x, Wu, bu, out);
}

// round 2
// speedup vs baseline: 1.4180x; 1.4180x over previous
#include <cuda_runtime.h>
#include <math.h>

#define B_  32
#define H_  56
#define W_  56
#define C_  192
#define D_  64
#define M_  8
#define HW_ 3136
#define N_  (B_*HW_)

typedef unsigned long long ull;

// ---------------- device scratch (no allocations allowed) ----------------
__device__ float g_pf[(size_t)N_ * 64];           // [n][64]
__device__ float g_xp[(size_t)B_ * D_ * HW_];     // [b][d][hw]
__device__ float g_logits[(size_t)M_ * B_ * HW_]; // [m][b][hw]
__device__ float g_stats[M_ * B_ * 2];            // per (m,b): max, 1/sum
__device__ float g_mwf[B_ * D_];                  // [b][64]
__device__ float g_convw[(size_t)B_ * D_ * D_ * 9]; // [b][oc][ic][3][3]

__device__ __forceinline__ float qgelu(float v) {
    return v / (1.f + __expf(-1.702f * v));
}
__device__ __forceinline__ ull dup2(float v) {
    ull r; asm("mov.b64 %0, {%1, %1};" : "=l"(r) : "f"(v)); return r;
}
__device__ __forceinline__ ull pk2(float lo, float hi) {
    ull r; asm("mov.b64 %0, {%1, %2};" : "=l"(r) : "f"(lo), "f"(hi)); return r;
}
__device__ __forceinline__ void unpk2(ull v, float& lo, float& hi) {
    asm("mov.b64 {%0, %1}, %2;" : "=f"(lo), "=f"(hi) : "l"(v));
}
__device__ __forceinline__ void fma2(ull& d, ull a, ull b) {
    asm("fma.rn.f32x2 %0, %1, %2, %0;" : "+l"(d) : "l"(a), "l"(b));
}
__device__ __forceinline__ unsigned sptr(const void* p) {
    return (unsigned)__cvta_generic_to_shared(p);
}
__device__ __forceinline__ void lds_v2u64(ull& a, ull& b, const float* p) {
    asm("ld.shared.v2.u64 {%0, %1}, [%2];" : "=l"(a), "=l"(b) : "r"(sptr(p)));
}
__device__ __forceinline__ ull lds_u64(const float* p) {
    ull r; asm("ld.shared.u64 %0, [%1];" : "=l"(r) : "r"(sptr(p))); return r;
}

// ============================================================================
// K1: fused  h = relu(x@W1^T+b1); xd = x@Wd^T+bd -> qgelu -> g_xp (transposed);
//            pf = h@W2^T + b2 -> g_pf;  logits[m] = pf . mask_token[m]
// block: 128 pos x 128 out, 256 threads, 8x8 thread tile, f32x2 packed
// ============================================================================
__global__ __launch_bounds__(256) void k1(
    const float* __restrict__ x, const float* __restrict__ W1, const float* __restrict__ b1,
    const float* __restrict__ W2, const float* __restrict__ b2, const float* __restrict__ mtok,
    const float* __restrict__ Wd, const float* __restrict__ bd)
{
    extern __shared__ float sm[];
    float* As = sm;              // 16*132
    float* Bs = sm + 2112;       // 16*132
    float* hs = sm + 4224;       // 128*66
    float* xs = sm + 12672;      // 64*132
    __shared__ float mt_s[M_ * 64];

    const int tid = threadIdx.x;
    const int b   = blockIdx.y;
    const int hw0 = blockIdx.x * 128;
    const int P   = min(128, HW_ - hw0);
    const int tx  = tid & 15;   // out group: o = tx*8 .. tx*8+7
    const int ty  = tid >> 4;   // pos group: p = ty + 16*i

    for (int i = tid; i < M_ * 64; i += 256) mt_s[i] = mtok[i];

    ull c1[8][4];
    #pragma unroll
    for (int i = 0; i < 8; i++)
        #pragma unroll
        for (int j = 0; j < 4; j++) c1[i][j] = 0ULL;

    const float* xb = x + (size_t)(b * HW_ + hw0) * C_;

    for (int k0 = 0; k0 < C_; k0 += 16) {
        __syncthreads();
        for (int i = tid; i < 2048; i += 256) {
            int p = i >> 4, kk = i & 15;
            As[kk * 132 + p] = (p < P) ? xb[(size_t)p * C_ + k0 + kk] : 0.f;
        }
        for (int i = tid; i < 2048; i += 256) {
            int o = i >> 4, kk = i & 15;
            float v = (o < 64) ? W1[o * C_ + k0 + kk] : Wd[(o - 64) * C_ + k0 + kk];
            Bs[kk * 132 + o] = v;
        }
        __syncthreads();
        #pragma unroll
        for (int kk = 0; kk < 16; kk++) {
            ull ad[8], bv[4];
            #pragma unroll
            for (int i = 0; i < 8; i++) ad[i] = dup2(As[kk * 132 + ty + 16 * i]);
            lds_v2u64(bv[0], bv[1], Bs + kk * 132 + tx * 8);
            lds_v2u64(bv[2], bv[3], Bs + kk * 132 + tx * 8 + 4);
            #pragma unroll
            for (int i = 0; i < 8; i++)
                #pragma unroll
                for (int j = 0; j < 4; j++) fma2(c1[i][j], ad[i], bv[j]);
        }
    }
    __syncthreads();

    // epilogue: h -> hs (relu); xd -> xs (qgelu)
    if (tx < 8) {
        #pragma unroll
        for (int j = 0; j < 4; j++) {
            int o = tx * 8 + 2 * j;
            float bia = b1[o], bib = b1[o + 1];
            #pragma unroll
            for (int i = 0; i < 8; i++) {
                int p = ty + 16 * i;
                float v0, v1; unpk2(c1[i][j], v0, v1);
                hs[p * 66 + o]     = fmaxf(v0 + bia, 0.f);
                hs[p * 66 + o + 1] = fmaxf(v1 + bib, 0.f);
            }
        }
    } else {
        #pragma unroll
        for (int j = 0; j < 4; j++) {
            int d = (tx - 8) * 8 + 2 * j;
            float bia = bd[d], bib = bd[d + 1];
            #pragma unroll
            for (int i = 0; i < 8; i++) {
                int p = ty + 16 * i;
                float v0, v1; unpk2(c1[i][j], v0, v1);
                xs[d * 132 + p]       = qgelu(v0 + bia);
                xs[(d + 1) * 132 + p] = qgelu(v1 + bib);
            }
        }
    }
    // stage W2 into As/Bs region: W2s[kk*66 + o]
    float* W2s = sm;
    for (int i = tid; i < 4096; i += 256) {
        int o = i >> 6, kk = i & 63;
        W2s[kk * 66 + o] = W2[o * 64 + kk];
    }
    __syncthreads();

    // coalesced xp write
    {
        float* xpb = g_xp + (size_t)b * D_ * HW_ + hw0;
        for (int i = tid; i < 8192; i += 256) {
            int d = i >> 7, p = i & 127;
            if (p < P) xpb[(size_t)d * HW_ + p] = xs[d * 132 + p];
        }
    }

    // pf = h @ W2^T : 128 pos x 64 out, thread tile 8 pos x 4 out (2 pairs)
    ull c2[8][2];
    #pragma unroll
    for (int i = 0; i < 8; i++) { c2[i][0] = 0ULL; c2[i][1] = 0ULL; }
    #pragma unroll 4
    for (int kk = 0; kk < 64; kk++) {
        ull ad[8], bv[2];
        #pragma unroll
        for (int i = 0; i < 8; i++) ad[i] = dup2(hs[(ty + 16 * i) * 66 + kk]);
        bv[0] = lds_u64(W2s + kk * 66 + tx * 4);
        bv[1] = lds_u64(W2s + kk * 66 + tx * 4 + 2);
        #pragma unroll
        for (int i = 0; i < 8; i++) { fma2(c2[i][0], ad[i], bv[0]); fma2(c2[i][1], ad[i], bv[1]); }
    }
    __syncthreads();   // all hs reads done before overwrite

    #pragma unroll
    for (int j = 0; j < 2; j++) {
        int o = tx * 4 + 2 * j;
        float bia = b2[o], bib = b2[o + 1];
        #pragma unroll
        for (int i = 0; i < 8; i++) {
            int p = ty + 16 * i;
            float v0, v1; unpk2(c2[i][j], v0, v1);
            v0 += bia; v1 += bib;
            hs[p * 66 + o] = v0; hs[p * 66 + o + 1] = v1;
            if (p < P) {
                float2* dst = (float2*)(g_pf + (size_t)(b * HW_ + hw0 + p) * 64 + o);
                *dst = make_float2(v0, v1);
            }
        }
    }
    __syncthreads();

    // logits: 128 pos x 8 masks
    #pragma unroll
    for (int q = 0; q < 4; q++) {
        int t = tid + 256 * q;
        int p = t & 127, m = t >> 7;
        float acc = 0.f;
        #pragma unroll 8
        for (int k = 0; k < 64; k++) acc = fmaf(hs[p * 66 + k], mt_s[m * 64 + k], acc);
        if (p < P) g_logits[(size_t)(m * B_ + b) * HW_ + hw0 + p] = acc;
    }
}

// ============================================================================
// K2: per-(m,b) softmax stats over 3136 positions
// ============================================================================
__global__ __launch_bounds__(128) void k2()
{
    int row = blockIdx.x;
    const float* l = g_logits + (size_t)row * HW_;
    __shared__ float red[128];
    int tid = threadIdx.x;

    float mx = -3.4e38f;
    for (int p = tid; p < HW_; p += 128) mx = fmaxf(mx, l[p]);
    red[tid] = mx; __syncthreads();
    for (int s = 64; s > 0; s >>= 1) {
        if (tid < s) red[tid] = fmaxf(red[tid], red[tid + s]);
        __syncthreads();
    }
    mx = red[0]; __syncthreads();

    float sum = 0.f;
    for (int p = tid; p < HW_; p += 128) sum += __expf(l[p] - mx);
    red[tid] = sum; __syncthreads();
    for (int s = 64; s > 0; s >>= 1) {
        if (tid < s) red[tid] += red[tid + s];
        __syncthreads();
    }
    if (tid == 0) { g_stats[row * 2] = mx; g_stats[row * 2 + 1] = 1.f / red[0]; }
}

// ============================================================================
// K3: masksum[b,p] = sum_m softmax ; mwf[b,k] = sum_p masksum * pf
// ============================================================================
__global__ __launch_bounds__(256) void k3()
{
    int b = blockIdx.x, tid = threadIdx.x;
    __shared__ float ms[HW_];
    __shared__ float mxs[M_], izs[M_];
    __shared__ float red[4][64];

    if (tid < M_) {
        mxs[tid] = g_stats[(tid * B_ + b) * 2];
        izs[tid] = g_stats[(tid * B_ + b) * 2 + 1];
    }
    __syncthreads();

    for (int p = tid; p < HW_; p += 256) {
        float s = 0.f;
        #pragma unroll
        for (int m = 0; m < M_; m++)
            s += __expf(g_logits[(size_t)(m * B_ + b) * HW_ + p] - mxs[m]) * izs[m];
        ms[p] = s;
    }
    __syncthreads();

    int k = tid & 63, g = tid >> 6;
    float acc = 0.f;
    const float* pfb = g_pf + (size_t)b * HW_ * 64;
    for (int p = g; p < HW_; p += 4)
        acc = fmaf(ms[p], pfb[(size_t)p * 64 + k], acc);
    red[g][k] = acc;
    __syncthreads();
    if (g == 0) g_mwf[b * 64 + k] = red[0][k] + red[1][k] + red[2][k] + red[3][k];
}

// ============================================================================
// K4: conv_w[b,o] = mwf[b] . Wh[o] + bh[o]  — Wh row in registers
// ============================================================================
__global__ __launch_bounds__(256) void k4(const float* __restrict__ Wh,
                                          const float* __restrict__ bh)
{
    __shared__ float ms[2048];
    int tid = threadIdx.x;
    for (int i = tid; i < 2048; i += 256) ms[i] = g_mwf[i];
    __syncthreads();

    int o = blockIdx.x * 256 + tid;
    float4 wv[16];
    const float4* wr = (const float4*)(Wh + (size_t)o * 64);
    #pragma unroll
    for (int i = 0; i < 16; i++) wv[i] = wr[i];
    const float* wf = (const float*)wv;
    float bias = bh[o];

    for (int b = 0; b < B_; b++) {
        float acc = bias;
        const float* mb = ms + b * 64;
        #pragma unroll
        for (int kk = 0; kk < 64; kk++) acc = fmaf(mb[kk], wf[kk], acc);
        g_convw[(size_t)b * 36864 + o] = acc;
    }
}

// ============================================================================
// K5: per-sample 3x3 conv (64->64) + quickGELU + up-proj + residual, fused.
// tile 8x28 positions, 224 threads, thread tile 8 pos x 8 oc, f32x2 packed,
// conv input/weights chunked over ic (2 chunks of 32).
// ============================================================================
__global__ __launch_bounds__(224, 1) void k5(const float* __restrict__ x,
                                             const float* __restrict__ Wu,
                                             const float* __restrict__ bu,
                                             float* __restrict__ out)
{
    extern __shared__ float sm[];
    float* cws  = sm;            // 288*68 = 19584  (per-chunk weights [k][oc])
    float* hbuf = sm + 19584;    // 32*10*30 = 9600 (per-chunk halo input)
    float* wus  = sm + 29184;    // 64*192 = 12288  (Wu transposed [d][c])
    float* gbuf = sm;            // overlay after conv: 224*68 = 15232

    const int tid = threadIdx.x;
    const int b = blockIdx.y;
    const int t = blockIdx.x;            // 0..13
    const int row0 = (t % 7) * 8;
    const int col0 = (t / 7) * 28;

    const int og   = tid / 28;           // 0..7  -> oc = og*8..og*8+7
    const int pg   = tid % 28;
    const int rgrp = pg / 7;             // rows 2*rgrp, 2*rgrp+1
    const int cgrp = pg % 7;             // cols 4*cgrp .. 4*cgrp+3

    // stage Wu transposed: wus[d*192 + c] = Wu[c*64 + d]
    for (int i = tid; i < 12288; i += 224) {
        int d = i / 192, c = i % 192;
        wus[i] = Wu[c * 64 + d];
        (void)d;
    }

    ull acc[2][4][4];
    #pragma unroll
    for (int dr = 0; dr < 2; dr++)
        #pragma unroll
        for (int dc = 0; dc < 4; dc++)
            #pragma unroll
            for (int j = 0; j < 4; j++) acc[dr][dc][j] = 0ULL;

    for (int ci = 0; ci < 2; ci++) {
        __syncthreads();
        // stage halo: hbuf[ic][r][c], 32 x 10 x 30
        for (int i = tid; i < 9600; i += 224) {
            int ic = i / 300, rem = i % 300;
            int r = rem / 30, cc = rem % 30;
            int gy = row0 - 1 + r, gx = col0 - 1 + cc;
            float v = 0.f;
            if (gy >= 0 && gy < H_ && gx >= 0 && gx < W_)
                v = g_xp[(size_t)(b * D_ + ci * 32 + ic) * HW_ + gy * W_ + gx];
            hbuf[i] = v;
        }
        // stage weights repacked: cws[(ic*9+tap)*68 + oc]
        for (int i = tid; i < 18432; i += 224) {
            int oc = i / 288, j = i % 288;
            cws[j * 68 + oc] = g_convw[(size_t)b * 36864 + oc * 576 + ci * 288 + j];
        }
        __syncthreads();

        for (int ic = 0; ic < 32; ic++) {
            const float* hb = hbuf + ic * 300 + rgrp * 60 + cgrp * 4;
            float patch[4][6];
            #pragma unroll
            for (int rr = 0; rr < 4; rr++)
                #pragma unroll
                for (int cc = 0; cc < 6; cc++) patch[rr][cc] = hb[rr * 30 + cc];
            const float* wp = cws + (ic * 9) * 68 + og * 8;
            #pragma unroll
            for (int tap = 0; tap < 9; tap++) {
                const int dy = tap / 3, dx = tap % 3;
                ull w0, w1, w2, w3;
                lds_v2u64(w0, w1, wp + tap * 68);
                lds_v2u64(w2, w3, wp + tap * 68 + 4);
                #pragma unroll
                for (int dr = 0; dr < 2; dr++)
                    #pragma unroll
                    for (int dc = 0; dc < 4; dc++) {
                        ull xd = dup2(patch[dr + dy][dc + dx]);
                        fma2(acc[dr][dc][0], xd, w0);
                        fma2(acc[dr][dc][1], xd, w1);
                        fma2(acc[dr][dc][2], xd, w2);
                        fma2(acc[dr][dc][3], xd, w3);
                    }
            }
        }
    }
    __syncthreads();   // conv done; cws/hbuf free

    // quickGELU -> gbuf[p*68 + oc]
    #pragma unroll
    for (int dr = 0; dr < 2; dr++)
        #pragma unroll
        for (int dc = 0; dc < 4; dc++) {
            int p = (2 * rgrp + dr) * 28 + 4 * cgrp + dc;
            #pragma unroll
            for (int j = 0; j < 4; j++) {
                float v0, v1; unpk2(acc[dr][dc][j], v0, v1);
                gbuf[p * 68 + og * 8 + 2 * j]     = qgelu(v0);
                gbuf[p * 68 + og * 8 + 2 * j + 1] = qgelu(v1);
            }
        }
    __syncthreads();

    // up-proj + residual: warp owns 32 positions (2 halves of 16);
    // lane owns channels c0..c0+5 (3 packed pairs)
    const int wid = tid >> 5, lane = tid & 31;
    const int c0 = lane * 6;
    for (int half = 0; half < 2; half++) {
        int pbase = wid * 32 + half * 16;
        ull a[16][3];
        int nidx[16];
        #pragma unroll
        for (int q = 0; q < 16; q++) {
            int p = pbase + q;
            int gy = row0 + p / 28, gx = col0 + p % 28;
            int n = b * HW_ + gy * W_ + gx;
            nidx[q] = n;
            const float* xr = x + (size_t)n * C_ + c0;
            a[q][0] = pk2(xr[0] + bu[c0],     xr[1] + bu[c0 + 1]);
            a[q][1] = pk2(xr[2] + bu[c0 + 2], xr[3] + bu[c0 + 3]);
            a[q][2] = pk2(xr[4] + bu[c0 + 4], xr[5] + bu[c0 + 5]);
        }
        #pragma unroll 2
        for (int d = 0; d < 64; d++) {
            ull wv0 = lds_u64(wus + d * 192 + c0);
            ull wv1 = lds_u64(wus + d * 192 + c0 + 2);
            ull wv2 = lds_u64(wus + d * 192 + c0 + 4);
            #pragma unroll
            for (int q = 0; q < 16; q++) {
                ull gd = dup2(gbuf[(pbase + q) * 68 + d]);
                fma2(a[q][0], gd, wv0);
                fma2(a[q][1], gd, wv1);
                fma2(a[q][2], gd, wv2);
            }
        }
        #pragma unroll
        for (int q = 0; q < 16; q++) {
            float* orr = out + (size_t)nidx[q] * C_ + c0;
            float v0, v1;
            unpk2(a[q][0], v0, v1); orr[0] = v0; orr[1] = v1;
            unpk2(a[q][1], v0, v1); orr[2] = v0; orr[3] = v1;
            unpk2(a[q][2], v0, v1); orr[4] = v0; orr[5] = v1;
        }
    }
}

// ============================================================================
extern "C" void kernel_launch(void* const* d_in, const int* in_sizes, int n_in,
                              void* d_out, int out_size)
{
    const float* x  = (const float*)d_in[0];
    const float* W1 = (const float*)d_in[1];
    const float* b1 = (const float*)d_in[2];
    const float* W2 = (const float*)d_in[3];
    const float* b2 = (const float*)d_in[4];
    const float* mt = (const float*)d_in[5];
    const float* Wh = (const float*)d_in[6];
    const float* bh = (const float*)d_in[7];
    const float* Wd = (const float*)d_in[8];
    const float* bd = (const float*)d_in[9];
    const float* Wu = (const float*)d_in[10];
    const float* bu = (const float*)d_in[11];
    float* out = (float*)d_out;

    cudaFuncSetAttribute(k1, cudaFuncAttributeMaxDynamicSharedMemorySize, 84480);
    cudaFuncSetAttribute(k5, cudaFuncAttributeMaxDynamicSharedMemorySize, 165888);

    k1<<<dim3(25, 32), 256, 84480>>>(x, W1, b1, W2, b2, mt, Wd, bd);
    k2<<<256, 128>>>();
    k3<<<32, 256>>>();
    k4<<<144, 256>>>(Wh, bh);
    k5<<<dim3(14, 32), 224, 165888>>>(x, Wu, bu, out);
}

// round 4
// speedup vs baseline: 1.9354x; 1.3649x over previous
#include <cuda_runtime.h>
#include <math.h>

#define B_  32
#define H_  56
#define W_  56
#define C_  192
#define D_  64
#define M_  8
#define HW_ 3136
#define N_  (B_*HW_)

typedef unsigned long long ull;

// ---------------- device scratch (no allocations allowed) ----------------
__device__ float g_pf[(size_t)N_ * 64];           // [n][64]
__device__ float g_xp[(size_t)B_ * D_ * HW_];     // [b][d][hw]
__device__ float g_logits[(size_t)M_ * B_ * HW_]; // [m][b][hw]
__device__ float g_stats[M_ * B_ * 2];            // per (m,b): max, 1/sum
__device__ float g_part[B_ * 8 * 64];             // partial mwf
__device__ float g_mwf[B_ * D_];                  // [b][64]
__device__ float g_convw[(size_t)B_ * D_ * D_ * 9]; // [b][oc][ic][3][3]

__device__ __forceinline__ float qgelu(float v) {
    return v / (1.f + __expf(-1.702f * v));
}
__device__ __forceinline__ ull dup2(float v) {
    ull r; asm("mov.b64 %0, {%1, %1};" : "=l"(r) : "f"(v)); return r;
}
__device__ __forceinline__ ull pk2(float lo, float hi) {
    ull r; asm("mov.b64 %0, {%1, %2};" : "=l"(r) : "f"(lo), "f"(hi)); return r;
}
__device__ __forceinline__ void unpk2(ull v, float& lo, float& hi) {
    asm("mov.b64 {%0, %1}, %2;" : "=f"(lo), "=f"(hi) : "l"(v));
}
__device__ __forceinline__ void fma2(ull& d, ull a, ull b) {
    asm("fma.rn.f32x2 %0, %1, %2, %0;" : "+l"(d) : "l"(a), "l"(b));
}
__device__ __forceinline__ unsigned sptr(const void* p) {
    return (unsigned)__cvta_generic_to_shared(p);
}
__device__ __forceinline__ void lds_v2u64(ull& a, ull& b, const float* p) {
    asm("ld.shared.v2.u64 {%0, %1}, [%2];" : "=l"(a), "=l"(b) : "r"(sptr(p)));
}
__device__ __forceinline__ ull lds_u64(const float* p) {
    ull r; asm("ld.shared.u64 %0, [%1];" : "=l"(r) : "r"(sptr(p))); return r;
}

// ============================================================================
// K1: fused  h = relu(x@W1^T+b1); xd = x@Wd^T+bd -> qgelu -> g_xp (transposed);
//            pf = h@W2^T + b2 -> g_pf;  logits[m] = pf . mask_token[m]
// ============================================================================
__global__ __launch_bounds__(256, 2) void k1(
    const float* __restrict__ x, const float* __restrict__ W1, const float* __restrict__ b1,
    const float* __restrict__ W2, const float* __restrict__ b2, const float* __restrict__ mtok,
    const float* __restrict__ Wd, const float* __restrict__ bd)
{
    extern __shared__ float sm[];
    float* As = sm;              // 16*132
    float* Bs = sm + 2112;       // 16*132
    float* hs = sm + 4224;       // 128*66
    float* xs = sm + 12672;      // 64*132
    __shared__ float mt_s[M_ * 64];

    const int tid = threadIdx.x;
    const int b   = blockIdx.y;
    const int hw0 = blockIdx.x * 128;
    const int P   = min(128, HW_ - hw0);
    const int tx  = tid & 15;
    const int ty  = tid >> 4;

    for (int i = tid; i < M_ * 64; i += 256) mt_s[i] = mtok[i];

    ull c1[8][4];
    #pragma unroll
    for (int i = 0; i < 8; i++)
        #pragma unroll
        for (int j = 0; j < 4; j++) c1[i][j] = 0ULL;

    const float* xb = x + (size_t)(b * HW_ + hw0) * C_;

    for (int k0 = 0; k0 < C_; k0 += 16) {
        __syncthreads();
        for (int i = tid; i < 2048; i += 256) {
            int p = i >> 4, kk = i & 15;
            As[kk * 132 + p] = (p < P) ? xb[(size_t)p * C_ + k0 + kk] : 0.f;
        }
        for (int i = tid; i < 2048; i += 256) {
            int o = i >> 4, kk = i & 15;
            float v = (o < 64) ? W1[o * C_ + k0 + kk] : Wd[(o - 64) * C_ + k0 + kk];
            Bs[kk * 132 + o] = v;
        }
        __syncthreads();
        #pragma unroll
        for (int kk = 0; kk < 16; kk++) {
            ull ad[8], bv[4];
            #pragma unroll
            for (int i = 0; i < 8; i++) ad[i] = dup2(As[kk * 132 + ty + 16 * i]);
            lds_v2u64(bv[0], bv[1], Bs + kk * 132 + tx * 8);
            lds_v2u64(bv[2], bv[3], Bs + kk * 132 + tx * 8 + 4);
            #pragma unroll
            for (int i = 0; i < 8; i++)
                #pragma unroll
                for (int j = 0; j < 4; j++) fma2(c1[i][j], ad[i], bv[j]);
        }
    }
    __syncthreads();

    if (tx < 8) {
        #pragma unroll
        for (int j = 0; j < 4; j++) {
            int o = tx * 8 + 2 * j;
            float bia = b1[o], bib = b1[o + 1];
            #pragma unroll
            for (int i = 0; i < 8; i++) {
                int p = ty + 16 * i;
                float v0, v1; unpk2(c1[i][j], v0, v1);
                hs[p * 66 + o]     = fmaxf(v0 + bia, 0.f);
                hs[p * 66 + o + 1] = fmaxf(v1 + bib, 0.f);
            }
        }
    } else {
        #pragma unroll
        for (int j = 0; j < 4; j++) {
            int d = (tx - 8) * 8 + 2 * j;
            float bia = bd[d], bib = bd[d + 1];
            #pragma unroll
            for (int i = 0; i < 8; i++) {
                int p = ty + 16 * i;
                float v0, v1; unpk2(c1[i][j], v0, v1);
                xs[d * 132 + p]       = qgelu(v0 + bia);
                xs[(d + 1) * 132 + p] = qgelu(v1 + bib);
            }
        }
    }
    float* W2s = sm;
    for (int i = tid; i < 4096; i += 256) {
        int o = i >> 6, kk = i & 63;
        W2s[kk * 66 + o] = W2[o * 64 + kk];
    }
    __syncthreads();

    {
        float* xpb = g_xp + (size_t)b * D_ * HW_ + hw0;
        for (int i = tid; i < 8192; i += 256) {
            int d = i >> 7, p = i & 127;
            if (p < P) xpb[(size_t)d * HW_ + p] = xs[d * 132 + p];
        }
    }

    ull c2[8][2];
    #pragma unroll
    for (int i = 0; i < 8; i++) { c2[i][0] = 0ULL; c2[i][1] = 0ULL; }
    #pragma unroll 4
    for (int kk = 0; kk < 64; kk++) {
        ull ad[8], bv[2];
        #pragma unroll
        for (int i = 0; i < 8; i++) ad[i] = dup2(hs[(ty + 16 * i) * 66 + kk]);
        bv[0] = lds_u64(W2s + kk * 66 + tx * 4);
        bv[1] = lds_u64(W2s + kk * 66 + tx * 4 + 2);
        #pragma unroll
        for (int i = 0; i < 8; i++) { fma2(c2[i][0], ad[i], bv[0]); fma2(c2[i][1], ad[i], bv[1]); }
    }
    __syncthreads();

    #pragma unroll
    for (int j = 0; j < 2; j++) {
        int o = tx * 4 + 2 * j;
        float bia = b2[o], bib = b2[o + 1];
        #pragma unroll
        for (int i = 0; i < 8; i++) {
            int p = ty + 16 * i;
            float v0, v1; unpk2(c2[i][j], v0, v1);
            v0 += bia; v1 += bib;
            hs[p * 66 + o] = v0; hs[p * 66 + o + 1] = v1;
            if (p < P) {
                float2* dst = (float2*)(g_pf + (size_t)(b * HW_ + hw0 + p) * 64 + o);
                *dst = make_float2(v0, v1);
            }
        }
    }
    __syncthreads();

    #pragma unroll
    for (int q = 0; q < 4; q++) {
        int t = tid + 256 * q;
        int p = t & 127, m = t >> 7;
        float acc = 0.f;
        #pragma unroll 8
        for (int k = 0; k < 64; k++) acc = fmaf(hs[p * 66 + k], mt_s[m * 64 + k], acc);
        if (p < P) g_logits[(size_t)(m * B_ + b) * HW_ + hw0 + p] = acc;
    }
}

// ============================================================================
// K2: per-(m,b) softmax stats over 3136 positions
// ============================================================================
__global__ __launch_bounds__(128) void k2()
{
    int row = blockIdx.x;
    const float* l = g_logits + (size_t)row * HW_;
    __shared__ float red[128];
    int tid = threadIdx.x;

    float mx = -3.4e38f;
    for (int p = tid; p < HW_; p += 128) mx = fmaxf(mx, l[p]);
    red[tid] = mx; __syncthreads();
    for (int s = 64; s > 0; s >>= 1) {
        if (tid < s) red[tid] = fmaxf(red[tid], red[tid + s]);
        __syncthreads();
    }
    mx = red[0]; __syncthreads();

    float sum = 0.f;
    for (int p = tid; p < HW_; p += 128) sum += __expf(l[p] - mx);
    red[tid] = sum; __syncthreads();
    for (int s = 64; s > 0; s >>= 1) {
        if (tid < s) red[tid] += red[tid + s];
        __syncthreads();
    }
    if (tid == 0) { g_stats[row * 2] = mx; g_stats[row * 2 + 1] = 1.f / red[0]; }
}

// ============================================================================
// K3a: partial mwf over 392-position chunks. grid (8, 32)
// ============================================================================
__global__ __launch_bounds__(256) void k3a()
{
    const int chunk = blockIdx.x, b = blockIdx.y;
    const int tid = threadIdx.x;
    const int p0 = chunk * 392;
    __shared__ float ms[392];
    __shared__ float mxs[M_], izs[M_];
    __shared__ float red[4][64];

    if (tid < M_) {
        mxs[tid] = g_stats[(tid * B_ + b) * 2];
        izs[tid] = g_stats[(tid * B_ + b) * 2 + 1];
    }
    __syncthreads();

    for (int p = tid; p < 392; p += 256) {
        float s = 0.f;
        #pragma unroll
        for (int m = 0; m < M_; m++)
            s += __expf(g_logits[(size_t)(m * B_ + b) * HW_ + p0 + p] - mxs[m]) * izs[m];
        ms[p] = s;
    }
    __syncthreads();

    int k = tid & 63, g = tid >> 6;
    float acc = 0.f;
    const float* pfb = g_pf + (size_t)(b * HW_ + p0) * 64;
    for (int p = g; p < 392; p += 4)
        acc = fmaf(ms[p], pfb[(size_t)p * 64 + k], acc);
    red[g][k] = acc;
    __syncthreads();
    if (g == 0)
        g_part[(b * 8 + chunk) * 64 + k] = red[0][k] + red[1][k] + red[2][k] + red[3][k];
}

// K3b: reduce partials -> g_mwf
__global__ __launch_bounds__(64) void k3b()
{
    int b = blockIdx.x, k = threadIdx.x;
    float acc = 0.f;
    #pragma unroll
    for (int c = 0; c < 8; c++) acc += g_part[(b * 8 + c) * 64 + k];
    g_mwf[b * 64 + k] = acc;
}

// ============================================================================
// K4: conv_w[b,o] = mwf[b] . Wh[o] + bh[o]
// ============================================================================
__global__ __launch_bounds__(256) void k4(const float* __restrict__ Wh,
                                          const float* __restrict__ bh)
{
    __shared__ float ms[2048];
    int tid = threadIdx.x;
    for (int i = tid; i < 2048; i += 256) ms[i] = g_mwf[i];
    __syncthreads();

    int o = blockIdx.x * 256 + tid;
    float4 wv[16];
    const float4* wr = (const float4*)(Wh + (size_t)o * 64);
    #pragma unroll
    for (int i = 0; i < 16; i++) wv[i] = wr[i];
    const float* wf = (const float*)wv;
    float bias = bh[o];

    for (int b = 0; b < B_; b++) {
        float acc = bias;
        const float* mb = ms + b * 64;
        #pragma unroll
        for (int kk = 0; kk < 64; kk++) acc = fmaf(mb[kk], wf[kk], acc);
        g_convw[(size_t)b * 36864 + o] = acc;
    }
}

// ============================================================================
// K5: per-sample 3x3 conv (64->64) + quickGELU + up-proj + residual, fused.
// tile 8x28 positions, 224 threads, ic chunked by 16 (4 chunks), 2 blocks/SM.
// wus stride = 194 (EVEN -> ld.shared.u64 stays 8B-aligned).
// ============================================================================
__global__ __launch_bounds__(224, 2) void k5(const float* __restrict__ x,
                                             const float* __restrict__ Wu,
                                             const float* __restrict__ bu,
                                             float* __restrict__ out)
{
    extern __shared__ float sm[];
    float* cws  = sm;            // 144*68 = 9792  (per-chunk weights [k][oc])
    float* hbuf = sm + 9792;     // 16*10*30 = 4800
    float* wus  = sm + 14592;    // 64*194 = 12416  (Wu transposed [d][c])
    float* gbuf = sm;            // overlay after conv: 224*65 = 14560

    const int tid = threadIdx.x;
    const int b = blockIdx.y;
    const int t = blockIdx.x;            // 0..13
    const int row0 = (t % 7) * 8;
    const int col0 = (t / 7) * 28;

    const int og   = tid / 28;           // oc = og*8..og*8+7
    const int pg   = tid % 28;
    const int rgrp = pg / 7;
    const int cgrp = pg % 7;

    // stage Wu transposed: wus[d*194 + c] = Wu[c*64 + d]
    for (int i = tid; i < 12416; i += 224) {
        int d = i / 194, c = i % 194;
        if (c < 192) wus[i] = Wu[c * 64 + d];
    }

    ull acc[2][4][4];
    #pragma unroll
    for (int dr = 0; dr < 2; dr++)
        #pragma unroll
        for (int dc = 0; dc < 4; dc++)
            #pragma unroll
            for (int j = 0; j < 4; j++) acc[dr][dc][j] = 0ULL;

    for (int ci = 0; ci < 4; ci++) {
        __syncthreads();
        // halo: hbuf[ic][r][c], 16 x 10 x 30
        for (int i = tid; i < 4800; i += 224) {
            int ic = i / 300, rem = i % 300;
            int r = rem / 30, cc = rem % 30;
            int gy = row0 - 1 + r, gx = col0 - 1 + cc;
            float v = 0.f;
            if (gy >= 0 && gy < H_ && gx >= 0 && gx < W_)
                v = g_xp[(size_t)(b * D_ + ci * 16 + ic) * HW_ + gy * W_ + gx];
            hbuf[i] = v;
        }
        // weights repacked: cws[(ic*9+tap)*68 + oc]
        for (int i = tid; i < 9216; i += 224) {
            int oc = i / 144, j = i % 144;
            cws[j * 68 + oc] = g_convw[(size_t)b * 36864 + oc * 576 + ci * 144 + j];
        }
        __syncthreads();

        for (int ic = 0; ic < 16; ic++) {
            const float* hb = hbuf + ic * 300 + rgrp * 60 + cgrp * 4;
            float patch[4][6];
            #pragma unroll
            for (int rr = 0; rr < 4; rr++)
                #pragma unroll
                for (int cc = 0; cc < 6; cc++) patch[rr][cc] = hb[rr * 30 + cc];
            const float* wp = cws + (ic * 9) * 68 + og * 8;
            #pragma unroll
            for (int tap = 0; tap < 9; tap++) {
                const int dy = tap / 3, dx = tap % 3;
                ull w0, w1, w2, w3;
                lds_v2u64(w0, w1, wp + tap * 68);
                lds_v2u64(w2, w3, wp + tap * 68 + 4);
                #pragma unroll
                for (int dr = 0; dr < 2; dr++)
                    #pragma unroll
                    for (int dc = 0; dc < 4; dc++) {
                        ull xd = dup2(patch[dr + dy][dc + dx]);
                        fma2(acc[dr][dc][0], xd, w0);
                        fma2(acc[dr][dc][1], xd, w1);
                        fma2(acc[dr][dc][2], xd, w2);
                        fma2(acc[dr][dc][3], xd, w3);
                    }
            }
        }
    }
    __syncthreads();   // conv done; cws/hbuf free

    // quickGELU -> gbuf[p*65 + oc]
    #pragma unroll
    for (int dr = 0; dr < 2; dr++)
        #pragma unroll
        for (int dc = 0; dc < 4; dc++) {
            int p = (2 * rgrp + dr) * 28 + 4 * cgrp + dc;
            #pragma unroll
            for (int j = 0; j < 4; j++) {
                float v0, v1; unpk2(acc[dr][dc][j], v0, v1);
                gbuf[p * 65 + og * 8 + 2 * j]     = qgelu(v0);
                gbuf[p * 65 + og * 8 + 2 * j + 1] = qgelu(v1);
            }
        }
    __syncthreads();

    // up-proj + residual: warp owns 32 positions, processed in 4 groups of 8;
    // lane owns channels c0..c0+5 (3 packed pairs)
    const int wid = tid >> 5, lane = tid & 31;
    const int c0 = lane * 6;
    for (int grp = 0; grp < 4; grp++) {
        int pbase = wid * 32 + grp * 8;
        ull a[8][3];
        int nidx[8];
        #pragma unroll
        for (int q = 0; q < 8; q++) {
            int p = pbase + q;
            int gy = row0 + p / 28, gx = col0 + p % 28;
            int n = b * HW_ + gy * W_ + gx;
            nidx[q] = n;
            const float* xr = x + (size_t)n * C_ + c0;
            a[q][0] = pk2(xr[0] + bu[c0],     xr[1] + bu[c0 + 1]);
            a[q][1] = pk2(xr[2] + bu[c0 + 2], xr[3] + bu[c0 + 3]);
            a[q][2] = pk2(xr[4] + bu[c0 + 4], xr[5] + bu[c0 + 5]);
        }
        #pragma unroll 4
        for (int d = 0; d < 64; d++) {
            ull wv0 = lds_u64(wus + d * 194 + c0);
            ull wv1 = lds_u64(wus + d * 194 + c0 + 2);
            ull wv2 = lds_u64(wus + d * 194 + c0 + 4);
            #pragma unroll
            for (int q = 0; q < 8; q++) {
                ull gd = dup2(gbuf[(pbase + q) * 65 + d]);
                fma2(a[q][0], gd, wv0);
                fma2(a[q][1], gd, wv1);
                fma2(a[q][2], gd, wv2);
            }
        }
        #pragma unroll
        for (int q = 0; q < 8; q++) {
            float* orr = out + (size_t)nidx[q] * C_ + c0;
            float v0, v1;
            unpk2(a[q][0], v0, v1); orr[0] = v0; orr[1] = v1;
            unpk2(a[q][1], v0, v1); orr[2] = v0; orr[3] = v1;
            unpk2(a[q][2], v0, v1); orr[4] = v0; orr[5] = v1;
        }
    }
}

// ============================================================================
extern "C" void kernel_launch(void* const* d_in, const int* in_sizes, int n_in,
                              void* d_out, int out_size)
{
    const float* x  = (const float*)d_in[0];
    const float* W1 = (const float*)d_in[1];
    const float* b1 = (const float*)d_in[2];
    const float* W2 = (const float*)d_in[3];
    const float* b2 = (const float*)d_in[4];
    const float* mt = (const float*)d_in[5];
    const float* Wh = (const float*)d_in[6];
    const float* bh = (const float*)d_in[7];
    const float* Wd = (const float*)d_in[8];
    const float* bd = (const float*)d_in[9];
    const float* Wu = (const float*)d_in[10];
    const float* bu = (const float*)d_in[11];
    float* out = (float*)d_out;

    cudaFuncSetAttribute(k1, cudaFuncAttributeMaxDynamicSharedMemorySize, 84480);
    cudaFuncSetAttribute(k5, cudaFuncAttributeMaxDynamicSharedMemorySize, 108288);

    k1<<<dim3(25, 32), 256, 84480>>>(x, W1, b1, W2, b2, mt, Wd, bd);
    k2<<<256, 128>>>();
    k3a<<<dim3(8, 32), 256>>>();
    k3b<<<32, 64>>>();
    k4<<<144, 256>>>(Wh, bh);
    k5<<<dim3(14, 32), 224, 108288>>>(x, Wu, bu, out);
}

// round 6
// speedup vs baseline: 2.0515x; 1.0600x over previous
#include <cuda_runtime.h>
#include <math.h>
#include <stdint.h>

#define B_  32
#define H_  56
#define W_  56
#define C_  192
#define D_  64
#define M_  8
#define HW_ 3136
#define N_  (B_*HW_)

typedef unsigned long long ull;

// ---------------- device scratch (no allocations allowed) ----------------
__device__ float g_pf[(size_t)N_ * 64];           // [n][64]
__device__ float g_xp[(size_t)B_ * D_ * HW_];     // [b][d][hw]
__device__ float g_logits[(size_t)M_ * B_ * HW_]; // [m][b][hw]
__device__ float g_stats[M_ * B_ * 2];            // per (m,b): max, 1/sum
__device__ float g_part[B_ * 8 * 64];             // partial mwf
__device__ float g_mwf[B_ * D_];                  // [b][64]
__device__ float g_convw[(size_t)B_ * D_ * D_ * 9]; // [b][oc][ic][3][3]

__device__ __forceinline__ float qgelu(float v) {
    return v / (1.f + __expf(-1.702f * v));
}
__device__ __forceinline__ ull dup2(float v) {
    ull r; asm("mov.b64 %0, {%1, %1};" : "=l"(r) : "f"(v)); return r;
}
__device__ __forceinline__ ull pk2(float lo, float hi) {
    ull r; asm("mov.b64 %0, {%1, %2};" : "=l"(r) : "f"(lo), "f"(hi)); return r;
}
__device__ __forceinline__ void unpk2(ull v, float& lo, float& hi) {
    asm("mov.b64 {%0, %1}, %2;" : "=f"(lo), "=f"(hi) : "l"(v));
}
__device__ __forceinline__ void fma2(ull& d, ull a, ull b) {
    asm("fma.rn.f32x2 %0, %1, %2, %0;" : "+l"(d) : "l"(a), "l"(b));
}
__device__ __forceinline__ unsigned sptr(const void* p) {
    return (unsigned)__cvta_generic_to_shared(p);
}
__device__ __forceinline__ void lds_v2u64(ull& a, ull& b, const float* p) {
    asm("ld.shared.v2.u64 {%0, %1}, [%2];" : "=l"(a), "=l"(b) : "r"(sptr(p)));
}
__device__ __forceinline__ ull lds_u64(const float* p) {
    ull r; asm("ld.shared.u64 %0, [%1];" : "=l"(r) : "r"(sptr(p))); return r;
}
__device__ __forceinline__ float tf32r(float v) {
    float r; asm("cvt.rna.tf32.f32 %0, %1;" : "=f"(r) : "f"(v)); return r;
}
// mma.sync m16n8k8 tf32 (baseline PTX, works on plain sm_103 target)
__device__ __forceinline__ void mma8(float* c, float a0, float a1, float a2, float a3,
                                     float b0, float b1) {
    asm volatile(
        "mma.sync.aligned.m16n8k8.row.col.f32.tf32.tf32.f32 "
        "{%0,%1,%2,%3}, {%4,%5,%6,%7}, {%8,%9}, {%0,%1,%2,%3};"
        : "+f"(c[0]), "+f"(c[1]), "+f"(c[2]), "+f"(c[3])
        : "r"(__float_as_uint(a0)), "r"(__float_as_uint(a1)),
          "r"(__float_as_uint(a2)), "r"(__float_as_uint(a3)),
          "r"(__float_as_uint(b0)), "r"(__float_as_uint(b1)));
}

// ============================================================================
// K1: D[128 pos][128 out] = x[128][192] @ [W1|Wd]^T via mma.sync tf32x3.
// Then cols 0-63 relu->hs; 64-127 qgelu->xs->g_xp; pf=hs@W2^T (f32x2); logits.
// 256 threads (8 warps); smem 84480B; 2 blocks/SM.
// ============================================================================
__global__ __launch_bounds__(256, 2) void k1(
    const float* __restrict__ x, const float* __restrict__ W1, const float* __restrict__ b1,
    const float* __restrict__ W2, const float* __restrict__ b2, const float* __restrict__ mtok,
    const float* __restrict__ Wd, const float* __restrict__ bd)
{
    extern __shared__ float sm[];
    // staging (floats): Ahi@0, Alo@4608, Bhi@9216, Blo@13824   (each 128*36)
    float* Ahi = sm, *Alo = sm + 4608, *Bhi = sm + 9216, *Blo = sm + 13824;
    // post-GEMM overlay: hs@0 (128*66), xs@8448 (64*132), W2s@16896 (64*66)
    float* hs = sm, *xs = sm + 8448, *W2s = sm + 16896;
    __shared__ float mt_s[M_ * 64];

    const int tid   = threadIdx.x;
    const int warp  = tid >> 5, lane = tid & 31;
    const int gID   = lane >> 2, tig = lane & 3;
    const int b     = blockIdx.y;
    const int hw0   = blockIdx.x * 128;
    const int P     = min(128, HW_ - hw0);

    for (int i = tid; i < M_ * 64; i += 256) mt_s[i] = mtok[i];

    float c[16][4];
    #pragma unroll
    for (int nt = 0; nt < 16; nt++)
        #pragma unroll
        for (int j = 0; j < 4; j++) c[nt][j] = 0.f;

    const float* xb = x + (size_t)(b * HW_ + hw0) * C_;

    for (int ch = 0; ch < 6; ch++) {
        const int k0 = ch * 32;
        __syncthreads();
        // stage A rows (x) hi/lo, tf32-rounded
        for (int i = tid; i < 1024; i += 256) {
            int r = i >> 3, q = i & 7;
            float4 v = make_float4(0.f, 0.f, 0.f, 0.f);
            if (r < P) v = *(const float4*)(xb + (size_t)r * C_ + k0 + q * 4);
            float4 hi, lo;
            hi.x = tf32r(v.x); lo.x = tf32r(v.x - hi.x);
            hi.y = tf32r(v.y); lo.y = tf32r(v.y - hi.y);
            hi.z = tf32r(v.z); lo.z = tf32r(v.z - hi.z);
            hi.w = tf32r(v.w); lo.w = tf32r(v.w - hi.w);
            *(float4*)(Ahi + r * 36 + q * 4) = hi;
            *(float4*)(Alo + r * 36 + q * 4) = lo;
        }
        // stage B rows (W1 0-63 | Wd 64-127) hi/lo
        for (int i = tid; i < 1024; i += 256) {
            int n = i >> 3, q = i & 7;
            const float* src = (n < 64) ? (W1 + n * C_) : (Wd + (n - 64) * C_);
            float4 v = *(const float4*)(src + k0 + q * 4);
            float4 hi, lo;
            hi.x = tf32r(v.x); lo.x = tf32r(v.x - hi.x);
            hi.y = tf32r(v.y); lo.y = tf32r(v.y - hi.y);
            hi.z = tf32r(v.z); lo.z = tf32r(v.z - hi.z);
            hi.w = tf32r(v.w); lo.w = tf32r(v.w - hi.w);
            *(float4*)(Bhi + n * 36 + q * 4) = hi;
            *(float4*)(Blo + n * 36 + q * 4) = lo;
        }
        __syncthreads();

        const int arow0 = warp * 16 + gID;
        #pragma unroll
        for (int ks = 0; ks < 4; ks++) {
            const int kk = ks * 8;
            float ah0 = Ahi[arow0 * 36 + kk + tig];
            float ah1 = Ahi[(arow0 + 8) * 36 + kk + tig];
            float ah2 = Ahi[arow0 * 36 + kk + tig + 4];
            float ah3 = Ahi[(arow0 + 8) * 36 + kk + tig + 4];
            float al0 = Alo[arow0 * 36 + kk + tig];
            float al1 = Alo[(arow0 + 8) * 36 + kk + tig];
            float al2 = Alo[arow0 * 36 + kk + tig + 4];
            float al3 = Alo[(arow0 + 8) * 36 + kk + tig + 4];
            #pragma unroll
            for (int nt = 0; nt < 16; nt++) {
                const int bn = nt * 8 + gID;
                float bh0 = Bhi[bn * 36 + kk + tig];
                float bh1 = Bhi[bn * 36 + kk + tig + 4];
                float bl0 = Blo[bn * 36 + kk + tig];
                float bl1 = Blo[bn * 36 + kk + tig + 4];
                mma8(c[nt], ah0, ah1, ah2, ah3, bh0, bh1);
                mma8(c[nt], ah0, ah1, ah2, ah3, bl0, bl1);
                mma8(c[nt], al0, al1, al2, al3, bh0, bh1);
            }
        }
    }
    __syncthreads();   // staging dead; overlay hs/xs

    // epilogue from accumulators
    {
        const int p0 = warp * 16 + gID, p1 = p0 + 8;
        #pragma unroll
        for (int nt = 0; nt < 16; nt++) {
            const int n = nt * 8 + tig * 2;
            if (nt < 8) {
                float bia = b1[n], bib = b1[n + 1];
                hs[p0 * 66 + n]     = fmaxf(c[nt][0] + bia, 0.f);
                hs[p0 * 66 + n + 1] = fmaxf(c[nt][1] + bib, 0.f);
                hs[p1 * 66 + n]     = fmaxf(c[nt][2] + bia, 0.f);
                hs[p1 * 66 + n + 1] = fmaxf(c[nt][3] + bib, 0.f);
            } else {
                const int d = n - 64;
                float bia = bd[d], bib = bd[d + 1];
                xs[d * 132 + p0]       = qgelu(c[nt][0] + bia);
                xs[(d + 1) * 132 + p0] = qgelu(c[nt][1] + bib);
                xs[d * 132 + p1]       = qgelu(c[nt][2] + bia);
                xs[(d + 1) * 132 + p1] = qgelu(c[nt][3] + bib);
            }
        }
    }
    // stage W2s (disjoint region)
    for (int i = tid; i < 4096; i += 256) {
        int o = i >> 6, kk = i & 63;
        W2s[kk * 66 + o] = W2[o * 64 + kk];
    }
    __syncthreads();

    // coalesced xp write
    {
        float* xpb = g_xp + (size_t)b * D_ * HW_ + hw0;
        for (int i = tid; i < 8192; i += 256) {
            int d = i >> 7, p = i & 127;
            if (p < P) xpb[(size_t)d * HW_ + p] = xs[d * 132 + p];
        }
    }

    // pf = hs @ W2^T : 128 pos x 64 out, thread tile 8 pos x 4 out, f32x2
    const int tx = tid & 15, ty = tid >> 4;
    ull c2[8][2];
    #pragma unroll
    for (int i = 0; i < 8; i++) { c2[i][0] = 0ULL; c2[i][1] = 0ULL; }
    #pragma unroll 4
    for (int kk = 0; kk < 64; kk++) {
        ull bv0 = lds_u64(W2s + kk * 66 + tx * 4);
        ull bv1 = lds_u64(W2s + kk * 66 + tx * 4 + 2);
        #pragma unroll
        for (int i = 0; i < 8; i++) {
            ull ad = dup2(hs[(ty + 16 * i) * 66 + kk]);
            fma2(c2[i][0], ad, bv0);
            fma2(c2[i][1], ad, bv1);
        }
    }
    __syncthreads();

    #pragma unroll
    for (int j = 0; j < 2; j++) {
        int o = tx * 4 + 2 * j;
        float bia = b2[o], bib = b2[o + 1];
        #pragma unroll
        for (int i = 0; i < 8; i++) {
            int p = ty + 16 * i;
            float v0, v1; unpk2(c2[i][j], v0, v1);
            v0 += bia; v1 += bib;
            hs[p * 66 + o] = v0; hs[p * 66 + o + 1] = v1;
            if (p < P) {
                float2* dst = (float2*)(g_pf + (size_t)(b * HW_ + hw0 + p) * 64 + o);
                *dst = make_float2(v0, v1);
            }
        }
    }
    __syncthreads();

    // logits: 128 pos x 8 masks
    #pragma unroll
    for (int q = 0; q < 4; q++) {
        int t = tid + 256 * q;
        int p = t & 127, m = t >> 7;
        float acc = 0.f;
        #pragma unroll 8
        for (int k = 0; k < 64; k++) acc = fmaf(hs[p * 66 + k], mt_s[m * 64 + k], acc);
        if (p < P) g_logits[(size_t)(m * B_ + b) * HW_ + hw0 + p] = acc;
    }
}

// ============================================================================
// K2: per-(m,b) softmax stats over 3136 positions
// ============================================================================
__global__ __launch_bounds__(128) void k2()
{
    int row = blockIdx.x;
    const float* l = g_logits + (size_t)row * HW_;
    __shared__ float red[128];
    int tid = threadIdx.x;

    float mx = -3.4e38f;
    for (int p = tid; p < HW_; p += 128) mx = fmaxf(mx, l[p]);
    red[tid] = mx; __syncthreads();
    for (int s = 64; s > 0; s >>= 1) {
        if (tid < s) red[tid] = fmaxf(red[tid], red[tid + s]);
        __syncthreads();
    }
    mx = red[0]; __syncthreads();

    float sum = 0.f;
    for (int p = tid; p < HW_; p += 128) sum += __expf(l[p] - mx);
    red[tid] = sum; __syncthreads();
    for (int s = 64; s > 0; s >>= 1) {
        if (tid < s) red[tid] += red[tid + s];
        __syncthreads();
    }
    if (tid == 0) { g_stats[row * 2] = mx; g_stats[row * 2 + 1] = 1.f / red[0]; }
}

// ============================================================================
// K3a: partial mwf over 392-position chunks. grid (8, 32)
// ============================================================================
__global__ __launch_bounds__(256) void k3a()
{
    const int chunk = blockIdx.x, b = blockIdx.y;
    const int tid = threadIdx.x;
    const int p0 = chunk * 392;
    __shared__ float ms[392];
    __shared__ float mxs[M_], izs[M_];
    __shared__ float red[4][64];

    if (tid < M_) {
        mxs[tid] = g_stats[(tid * B_ + b) * 2];
        izs[tid] = g_stats[(tid * B_ + b) * 2 + 1];
    }
    __syncthreads();

    for (int p = tid; p < 392; p += 256) {
        float s = 0.f;
        #pragma unroll
        for (int m = 0; m < M_; m++)
            s += __expf(g_logits[(size_t)(m * B_ + b) * HW_ + p0 + p] - mxs[m]) * izs[m];
        ms[p] = s;
    }
    __syncthreads();

    int k = tid & 63, g = tid >> 6;
    float acc = 0.f;
    const float* pfb = g_pf + (size_t)(b * HW_ + p0) * 64;
    for (int p = g; p < 392; p += 4)
        acc = fmaf(ms[p], pfb[(size_t)p * 64 + k], acc);
    red[g][k] = acc;
    __syncthreads();
    if (g == 0)
        g_part[(b * 8 + chunk) * 64 + k] = red[0][k] + red[1][k] + red[2][k] + red[3][k];
}

// K3b: reduce partials -> g_mwf
__global__ __launch_bounds__(64) void k3b()
{
    int b = blockIdx.x, k = threadIdx.x;
    float acc = 0.f;
    #pragma unroll
    for (int c = 0; c < 8; c++) acc += g_part[(b * 8 + c) * 64 + k];
    g_mwf[b * 64 + k] = acc;
}

// ============================================================================
// K4: conv_w[b,o] = mwf[b] . Wh[o] + bh[o]
// ============================================================================
__global__ __launch_bounds__(256) void k4(const float* __restrict__ Wh,
                                          const float* __restrict__ bh)
{
    __shared__ float ms[2048];
    int tid = threadIdx.x;
    for (int i = tid; i < 2048; i += 256) ms[i] = g_mwf[i];
    __syncthreads();

    int o = blockIdx.x * 256 + tid;
    float4 wv[16];
    const float4* wr = (const float4*)(Wh + (size_t)o * 64);
    #pragma unroll
    for (int i = 0; i < 16; i++) wv[i] = wr[i];
    const float* wf = (const float*)wv;
    float bias = bh[o];

    for (int b = 0; b < B_; b++) {
        float acc = bias;
        const float* mb = ms + b * 64;
        #pragma unroll
        for (int kk = 0; kk < 64; kk++) acc = fmaf(mb[kk], wf[kk], acc);
        g_convw[(size_t)b * 36864 + o] = acc;
    }
}

// ============================================================================
// K5: per-sample 3x3 conv (64->64) + quickGELU + up-proj + residual, fused.
// tile 8x28 positions, 224 threads, ic chunked by 16 (4 chunks), 2 blocks/SM.
// ============================================================================
__global__ __launch_bounds__(224, 2) void k5(const float* __restrict__ x,
                                             const float* __restrict__ Wu,
                                             const float* __restrict__ bu,
                                             float* __restrict__ out)
{
    extern __shared__ float sm[];
    float* cws  = sm;            // 144*68 = 9792
    float* hbuf = sm + 9792;     // 16*10*30 = 4800
    float* wus  = sm + 14592;    // 64*194 = 12416
    float* gbuf = sm;            // overlay after conv: 224*65 = 14560

    const int tid = threadIdx.x;
    const int b = blockIdx.y;
    const int t = blockIdx.x;
    const int row0 = (t % 7) * 8;
    const int col0 = (t / 7) * 28;

    const int og   = tid / 28;
    const int pg   = tid % 28;
    const int rgrp = pg / 7;
    const int cgrp = pg % 7;

    for (int i = tid; i < 12416; i += 224) {
        int d = i / 194, c = i % 194;
        if (c < 192) wus[i] = Wu[c * 64 + d];
    }

    ull acc[2][4][4];
    #pragma unroll
    for (int dr = 0; dr < 2; dr++)
        #pragma unroll
        for (int dc = 0; dc < 4; dc++)
            #pragma unroll
            for (int j = 0; j < 4; j++) acc[dr][dc][j] = 0ULL;

    for (int ci = 0; ci < 4; ci++) {
        __syncthreads();
        for (int i = tid; i < 4800; i += 224) {
            int ic = i / 300, rem = i % 300;
            int r = rem / 30, cc = rem % 30;
            int gy = row0 - 1 + r, gx = col0 - 1 + cc;
            float v = 0.f;
            if (gy >= 0 && gy < H_ && gx >= 0 && gx < W_)
                v = g_xp[(size_t)(b * D_ + ci * 16 + ic) * HW_ + gy * W_ + gx];
            hbuf[i] = v;
        }
        for (int i = tid; i < 9216; i += 224) {
            int oc = i / 144, j = i % 144;
            cws[j * 68 + oc] = g_convw[(size_t)b * 36864 + oc * 576 + ci * 144 + j];
        }
        __syncthreads();

        for (int ic = 0; ic < 16; ic++) {
            const float* hb = hbuf + ic * 300 + rgrp * 60 + cgrp * 4;
            float patch[4][6];
            #pragma unroll
            for (int rr = 0; rr < 4; rr++)
                #pragma unroll
                for (int cc = 0; cc < 6; cc++) patch[rr][cc] = hb[rr * 30 + cc];
            const float* wp = cws + (ic * 9) * 68 + og * 8;
            #pragma unroll
            for (int tap = 0; tap < 9; tap++) {
                const int dy = tap / 3, dx = tap % 3;
                ull w0, w1, w2, w3;
                lds_v2u64(w0, w1, wp + tap * 68);
                lds_v2u64(w2, w3, wp + tap * 68 + 4);
                #pragma unroll
                for (int dr = 0; dr < 2; dr++)
                    #pragma unroll
                    for (int dc = 0; dc < 4; dc++) {
                        ull xd = dup2(patch[dr + dy][dc + dx]);
                        fma2(acc[dr][dc][0], xd, w0);
                        fma2(acc[dr][dc][1], xd, w1);
                        fma2(acc[dr][dc][2], xd, w2);
                        fma2(acc[dr][dc][3], xd, w3);
                    }
            }
        }
    }
    __syncthreads();

    #pragma unroll
    for (int dr = 0; dr < 2; dr++)
        #pragma unroll
        for (int dc = 0; dc < 4; dc++) {
            int p = (2 * rgrp + dr) * 28 + 4 * cgrp + dc;
            #pragma unroll
            for (int j = 0; j < 4; j++) {
                float v0, v1; unpk2(acc[dr][dc][j], v0, v1);
                gbuf[p * 65 + og * 8 + 2 * j]     = qgelu(v0);
                gbuf[p * 65 + og * 8 + 2 * j + 1] = qgelu(v1);
            }
        }
    __syncthreads();

    const int wid = tid >> 5, lane = tid & 31;
    const int c0 = lane * 6;
    for (int grp = 0; grp < 4; grp++) {
        int pbase = wid * 32 + grp * 8;
        ull a[8][3];
        int nidx[8];
        #pragma unroll
        for (int q = 0; q < 8; q++) {
            int p = pbase + q;
            int gy = row0 + p / 28, gx = col0 + p % 28;
            int n = b * HW_ + gy * W_ + gx;
            nidx[q] = n;
            const float* xr = x + (size_t)n * C_ + c0;
            a[q][0] = pk2(xr[0] + bu[c0],     xr[1] + bu[c0 + 1]);
            a[q][1] = pk2(xr[2] + bu[c0 + 2], xr[3] + bu[c0 + 3]);
            a[q][2] = pk2(xr[4] + bu[c0 + 4], xr[5] + bu[c0 + 5]);
        }
        #pragma unroll 4
        for (int d = 0; d < 64; d++) {
            ull wv0 = lds_u64(wus + d * 194 + c0);
            ull wv1 = lds_u64(wus + d * 194 + c0 + 2);
            ull wv2 = lds_u64(wus + d * 194 + c0 + 4);
            #pragma unroll
            for (int q = 0; q < 8; q++) {
                ull gd = dup2(gbuf[(pbase + q) * 65 + d]);
                fma2(a[q][0], gd, wv0);
                fma2(a[q][1], gd, wv1);
                fma2(a[q][2], gd, wv2);
            }
        }
        #pragma unroll
        for (int q = 0; q < 8; q++) {
            float* orr = out + (size_t)nidx[q] * C_ + c0;
            float v0, v1;
            unpk2(a[q][0], v0, v1); orr[0] = v0; orr[1] = v1;
            unpk2(a[q][1], v0, v1); orr[2] = v0; orr[3] = v1;
            unpk2(a[q][2], v0, v1); orr[4] = v0; orr[5] = v1;
        }
    }
}

// ============================================================================
extern "C" void kernel_launch(void* const* d_in, const int* in_sizes, int n_in,
                              void* d_out, int out_size)
{
    const float* x  = (const float*)d_in[0];
    const float* W1 = (const float*)d_in[1];
    const float* b1 = (const float*)d_in[2];
    const float* W2 = (const float*)d_in[3];
    const float* b2 = (const float*)d_in[4];
    const float* mt = (const float*)d_in[5];
    const float* Wh = (const float*)d_in[6];
    const float* bh = (const float*)d_in[7];
    const float* Wd = (const float*)d_in[8];
    const float* bd = (const float*)d_in[9];
    const float* Wu = (const float*)d_in[10];
    const float* bu = (const float*)d_in[11];
    float* out = (float*)d_out;

    cudaFuncSetAttribute(k1, cudaFuncAttributeMaxDynamicSharedMemorySize, 84480);
    cudaFuncSetAttribute(k5, cudaFuncAttributeMaxDynamicSharedMemorySize, 108288);

    k1<<<dim3(25, 32), 256, 84480>>>(x, W1, b1, W2, b2, mt, Wd, bd);
    k2<<<256, 128>>>();
    k3a<<<dim3(8, 32), 256>>>();
    k3b<<<32, 64>>>();
    k4<<<144, 256>>>(Wh, bh);
    k5<<<dim3(14, 32), 224, 108288>>>(x, Wu, bu, out);
}

// round 7
// speedup vs baseline: 2.5618x; 1.2487x over previous
#include <cuda_runtime.h>
#include <cuda_fp16.h>
#include <math.h>
#include <stdint.h>

#define B_  32
#define H_  56
#define W_  56
#define C_  192
#define D_  64
#define M_  8
#define HW_ 3136
#define N_  (B_*HW_)

typedef unsigned long long ull;

// ---------------- device scratch (no allocations allowed) ----------------
__device__ float g_pf[(size_t)N_ * 64];           // [n][64]
__device__ float g_xp[(size_t)B_ * D_ * HW_];     // [b][d][hw]
__device__ float g_logits[(size_t)M_ * B_ * HW_]; // [m][b][hw]
__device__ float g_stats[M_ * B_ * 2];            // per (m,b): max, 1/sum
__device__ float g_part[B_ * 8 * 64];             // partial mwf
__device__ float g_mwf[B_ * D_];                  // [b][64]
__device__ float g_convw[(size_t)B_ * D_ * D_ * 9]; // [b][oc][ic][3][3]

__device__ __forceinline__ float qgelu(float v) {
    return v / (1.f + __expf(-1.702f * v));
}
__device__ __forceinline__ ull dup2(float v) {
    ull r; asm("mov.b64 %0, {%1, %1};" : "=l"(r) : "f"(v)); return r;
}
__device__ __forceinline__ ull pk2(float lo, float hi) {
    ull r; asm("mov.b64 %0, {%1, %2};" : "=l"(r) : "f"(lo), "f"(hi)); return r;
}
__device__ __forceinline__ void unpk2(ull v, float& lo, float& hi) {
    asm("mov.b64 {%0, %1}, %2;" : "=f"(lo), "=f"(hi) : "l"(v));
}
__device__ __forceinline__ void fma2(ull& d, ull a, ull b) {
    asm("fma.rn.f32x2 %0, %1, %2, %0;" : "+l"(d) : "l"(a), "l"(b));
}
__device__ __forceinline__ unsigned sptr(const void* p) {
    return (unsigned)__cvta_generic_to_shared(p);
}
__device__ __forceinline__ void lds_v2u64(ull& a, ull& b, const float* p) {
    asm("ld.shared.v2.u64 {%0, %1}, [%2];" : "=l"(a), "=l"(b) : "r"(sptr(p)));
}
__device__ __forceinline__ ull lds_u64(const float* p) {
    ull r; asm("ld.shared.u64 %0, [%1];" : "=l"(r) : "r"(sptr(p))); return r;
}
__device__ __forceinline__ float tf32r(float v) {
    float r; asm("cvt.rna.tf32.f32 %0, %1;" : "=f"(r) : "f"(v)); return r;
}
// mma.sync m16n8k8 tf32 (baseline PTX, works on plain sm_103 target)
__device__ __forceinline__ void mma8(float* c, float a0, float a1, float a2, float a3,
                                     float b0, float b1) {
    asm volatile(
        "mma.sync.aligned.m16n8k8.row.col.f32.tf32.tf32.f32 "
        "{%0,%1,%2,%3}, {%4,%5,%6,%7}, {%8,%9}, {%0,%1,%2,%3};"
        : "+f"(c[0]), "+f"(c[1]), "+f"(c[2]), "+f"(c[3])
        : "r"(__float_as_uint(a0)), "r"(__float_as_uint(a1)),
          "r"(__float_as_uint(a2)), "r"(__float_as_uint(a3)),
          "r"(__float_as_uint(b0)), "r"(__float_as_uint(b1)));
}

// ============================================================================
// K1: D[128 pos][128 out] = x[128][192] @ [W1|Wd]^T via mma.sync tf32x3.
// (unchanged from the passing round-6 kernel)
// ============================================================================
__global__ __launch_bounds__(256, 2) void k1(
    const float* __restrict__ x, const float* __restrict__ W1, const float* __restrict__ b1,
    const float* __restrict__ W2, const float* __restrict__ b2, const float* __restrict__ mtok,
    const float* __restrict__ Wd, const float* __restrict__ bd)
{
    extern __shared__ float sm[];
    float* Ahi = sm, *Alo = sm + 4608, *Bhi = sm + 9216, *Blo = sm + 13824;
    float* hs = sm, *xs = sm + 8448, *W2s = sm + 16896;
    __shared__ float mt_s[M_ * 64];

    const int tid   = threadIdx.x;
    const int warp  = tid >> 5, lane = tid & 31;
    const int gID   = lane >> 2, tig = lane & 3;
    const int b     = blockIdx.y;
    const int hw0   = blockIdx.x * 128;
    const int P     = min(128, HW_ - hw0);

    for (int i = tid; i < M_ * 64; i += 256) mt_s[i] = mtok[i];

    float c[16][4];
    #pragma unroll
    for (int nt = 0; nt < 16; nt++)
        #pragma unroll
        for (int j = 0; j < 4; j++) c[nt][j] = 0.f;

    const float* xb = x + (size_t)(b * HW_ + hw0) * C_;

    for (int ch = 0; ch < 6; ch++) {
        const int k0 = ch * 32;
        __syncthreads();
        for (int i = tid; i < 1024; i += 256) {
            int r = i >> 3, q = i & 7;
            float4 v = make_float4(0.f, 0.f, 0.f, 0.f);
            if (r < P) v = *(const float4*)(xb + (size_t)r * C_ + k0 + q * 4);
            float4 hi, lo;
            hi.x = tf32r(v.x); lo.x = tf32r(v.x - hi.x);
            hi.y = tf32r(v.y); lo.y = tf32r(v.y - hi.y);
            hi.z = tf32r(v.z); lo.z = tf32r(v.z - hi.z);
            hi.w = tf32r(v.w); lo.w = tf32r(v.w - hi.w);
            *(float4*)(Ahi + r * 36 + q * 4) = hi;
            *(float4*)(Alo + r * 36 + q * 4) = lo;
        }
        for (int i = tid; i < 1024; i += 256) {
            int n = i >> 3, q = i & 7;
            const float* src = (n < 64) ? (W1 + n * C_) : (Wd + (n - 64) * C_);
            float4 v = *(const float4*)(src + k0 + q * 4);
            float4 hi, lo;
            hi.x = tf32r(v.x); lo.x = tf32r(v.x - hi.x);
            hi.y = tf32r(v.y); lo.y = tf32r(v.y - hi.y);
            hi.z = tf32r(v.z); lo.z = tf32r(v.z - hi.z);
            hi.w = tf32r(v.w); lo.w = tf32r(v.w - hi.w);
            *(float4*)(Bhi + n * 36 + q * 4) = hi;
            *(float4*)(Blo + n * 36 + q * 4) = lo;
        }
        __syncthreads();

        const int arow0 = warp * 16 + gID;
        #pragma unroll
        for (int ks = 0; ks < 4; ks++) {
            const int kk = ks * 8;
            float ah0 = Ahi[arow0 * 36 + kk + tig];
            float ah1 = Ahi[(arow0 + 8) * 36 + kk + tig];
            float ah2 = Ahi[arow0 * 36 + kk + tig + 4];
            float ah3 = Ahi[(arow0 + 8) * 36 + kk + tig + 4];
            float al0 = Alo[arow0 * 36 + kk + tig];
            float al1 = Alo[(arow0 + 8) * 36 + kk + tig];
            float al2 = Alo[arow0 * 36 + kk + tig + 4];
            float al3 = Alo[(arow0 + 8) * 36 + kk + tig + 4];
            #pragma unroll
            for (int nt = 0; nt < 16; nt++) {
                const int bn = nt * 8 + gID;
                float bh0 = Bhi[bn * 36 + kk + tig];
                float bh1 = Bhi[bn * 36 + kk + tig + 4];
                float bl0 = Blo[bn * 36 + kk + tig];
                float bl1 = Blo[bn * 36 + kk + tig + 4];
                mma8(c[nt], ah0, ah1, ah2, ah3, bh0, bh1);
                mma8(c[nt], ah0, ah1, ah2, ah3, bl0, bl1);
                mma8(c[nt], al0, al1, al2, al3, bh0, bh1);
            }
        }
    }
    __syncthreads();

    {
        const int p0 = warp * 16 + gID, p1 = p0 + 8;
        #pragma unroll
        for (int nt = 0; nt < 16; nt++) {
            const int n = nt * 8 + tig * 2;
            if (nt < 8) {
                float bia = b1[n], bib = b1[n + 1];
                hs[p0 * 66 + n]     = fmaxf(c[nt][0] + bia, 0.f);
                hs[p0 * 66 + n + 1] = fmaxf(c[nt][1] + bib, 0.f);
                hs[p1 * 66 + n]     = fmaxf(c[nt][2] + bia, 0.f);
                hs[p1 * 66 + n + 1] = fmaxf(c[nt][3] + bib, 0.f);
            } else {
                const int d = n - 64;
                float bia = bd[d], bib = bd[d + 1];
                xs[d * 132 + p0]       = qgelu(c[nt][0] + bia);
                xs[(d + 1) * 132 + p0] = qgelu(c[nt][1] + bib);
                xs[d * 132 + p1]       = qgelu(c[nt][2] + bia);
                xs[(d + 1) * 132 + p1] = qgelu(c[nt][3] + bib);
            }
        }
    }
    for (int i = tid; i < 4096; i += 256) {
        int o = i >> 6, kk = i & 63;
        W2s[kk * 66 + o] = W2[o * 64 + kk];
    }
    __syncthreads();

    {
        float* xpb = g_xp + (size_t)b * D_ * HW_ + hw0;
        for (int i = tid; i < 8192; i += 256) {
            int d = i >> 7, p = i & 127;
            if (p < P) xpb[(size_t)d * HW_ + p] = xs[d * 132 + p];
        }
    }

    const int tx = tid & 15, ty = tid >> 4;
    ull c2[8][2];
    #pragma unroll
    for (int i = 0; i < 8; i++) { c2[i][0] = 0ULL; c2[i][1] = 0ULL; }
    #pragma unroll 4
    for (int kk = 0; kk < 64; kk++) {
        ull bv0 = lds_u64(W2s + kk * 66 + tx * 4);
        ull bv1 = lds_u64(W2s + kk * 66 + tx * 4 + 2);
        #pragma unroll
        for (int i = 0; i < 8; i++) {
            ull ad = dup2(hs[(ty + 16 * i) * 66 + kk]);
            fma2(c2[i][0], ad, bv0);
            fma2(c2[i][1], ad, bv1);
        }
    }
    __syncthreads();

    #pragma unroll
    for (int j = 0; j < 2; j++) {
        int o = tx * 4 + 2 * j;
        float bia = b2[o], bib = b2[o + 1];
        #pragma unroll
        for (int i = 0; i < 8; i++) {
            int p = ty + 16 * i;
            float v0, v1; unpk2(c2[i][j], v0, v1);
            v0 += bia; v1 += bib;
            hs[p * 66 + o] = v0; hs[p * 66 + o + 1] = v1;
            if (p < P) {
                float2* dst = (float2*)(g_pf + (size_t)(b * HW_ + hw0 + p) * 64 + o);
                *dst = make_float2(v0, v1);
            }
        }
    }
    __syncthreads();

    #pragma unroll
    for (int q = 0; q < 4; q++) {
        int t = tid + 256 * q;
        int p = t & 127, m = t >> 7;
        float acc = 0.f;
        #pragma unroll 8
        for (int k = 0; k < 64; k++) acc = fmaf(hs[p * 66 + k], mt_s[m * 64 + k], acc);
        if (p < P) g_logits[(size_t)(m * B_ + b) * HW_ + hw0 + p] = acc;
    }
}

// ============================================================================
// K2: per-(m,b) softmax stats over 3136 positions
// ============================================================================
__global__ __launch_bounds__(128) void k2()
{
    int row = blockIdx.x;
    const float* l = g_logits + (size_t)row * HW_;
    __shared__ float red[128];
    int tid = threadIdx.x;

    float mx = -3.4e38f;
    for (int p = tid; p < HW_; p += 128) mx = fmaxf(mx, l[p]);
    red[tid] = mx; __syncthreads();
    for (int s = 64; s > 0; s >>= 1) {
        if (tid < s) red[tid] = fmaxf(red[tid], red[tid + s]);
        __syncthreads();
    }
    mx = red[0]; __syncthreads();

    float sum = 0.f;
    for (int p = tid; p < HW_; p += 128) sum += __expf(l[p] - mx);
    red[tid] = sum; __syncthreads();
    for (int s = 64; s > 0; s >>= 1) {
        if (tid < s) red[tid] += red[tid + s];
        __syncthreads();
    }
    if (tid == 0) { g_stats[row * 2] = mx; g_stats[row * 2 + 1] = 1.f / red[0]; }
}

// ============================================================================
// K3a: partial mwf over 392-position chunks. grid (8, 32)
// ============================================================================
__global__ __launch_bounds__(256) void k3a()
{
    const int chunk = blockIdx.x, b = blockIdx.y;
    const int tid = threadIdx.x;
    const int p0 = chunk * 392;
    __shared__ float ms[392];
    __shared__ float mxs[M_], izs[M_];
    __shared__ float red[4][64];

    if (tid < M_) {
        mxs[tid] = g_stats[(tid * B_ + b) * 2];
        izs[tid] = g_stats[(tid * B_ + b) * 2 + 1];
    }
    __syncthreads();

    for (int p = tid; p < 392; p += 256) {
        float s = 0.f;
        #pragma unroll
        for (int m = 0; m < M_; m++)
            s += __expf(g_logits[(size_t)(m * B_ + b) * HW_ + p0 + p] - mxs[m]) * izs[m];
        ms[p] = s;
    }
    __syncthreads();

    int k = tid & 63, g = tid >> 6;
    float acc = 0.f;
    const float* pfb = g_pf + (size_t)(b * HW_ + p0) * 64;
    for (int p = g; p < 392; p += 4)
        acc = fmaf(ms[p], pfb[(size_t)p * 64 + k], acc);
    red[g][k] = acc;
    __syncthreads();
    if (g == 0)
        g_part[(b * 8 + chunk) * 64 + k] = red[0][k] + red[1][k] + red[2][k] + red[3][k];
}

// K3b: reduce partials -> g_mwf
__global__ __launch_bounds__(64) void k3b()
{
    int b = blockIdx.x, k = threadIdx.x;
    float acc = 0.f;
    #pragma unroll
    for (int c = 0; c < 8; c++) acc += g_part[(b * 8 + c) * 64 + k];
    g_mwf[b * 64 + k] = acc;
}

// ============================================================================
// K4: conv_w[b,o] = mwf[b] . Wh[o] + bh[o]
// ============================================================================
__global__ __launch_bounds__(256) void k4(const float* __restrict__ Wh,
                                          const float* __restrict__ bh)
{
    __shared__ float ms[2048];
    int tid = threadIdx.x;
    for (int i = tid; i < 2048; i += 256) ms[i] = g_mwf[i];
    __syncthreads();

    int o = blockIdx.x * 256 + tid;
    float4 wv[16];
    const float4* wr = (const float4*)(Wh + (size_t)o * 64);
    #pragma unroll
    for (int i = 0; i < 16; i++) wv[i] = wr[i];
    const float* wf = (const float*)wv;
    float bias = bh[o];

    for (int b = 0; b < B_; b++) {
        float acc = bias;
        const float* mb = ms + b * 64;
        #pragma unroll
        for (int kk = 0; kk < 64; kk++) acc = fmaf(mb[kk], wf[kk], acc);
        g_convw[(size_t)b * 36864 + o] = acc;
    }
}

// ============================================================================
// K5: per-sample 3x3 conv via mma.sync tf32 (implicit GEMM, 1-term) +
//     quickGELU (half2 smem) + up-proj (f32x2) + residual.
// tile 8 rows x 32 cols = 256 positions (col-major m = c*8+r), 256 threads,
// 8 warps: warp owns 2 m-tiles x 8 n-tiles. ic chunked by 16 (4 chunks).
// col tiles overlap (col0 in {0,24}) -> duplicate identical writes (benign).
// ============================================================================
__global__ __launch_bounds__(256, 2) void k5(const float* __restrict__ x,
                                             const float* __restrict__ Wu,
                                             const float* __restrict__ bu,
                                             float* __restrict__ out)
{
    extern __shared__ float sm[];
    float* hin = sm;                 // [340 spatial][18] (16 ic + pad)
    float* Bw  = sm + 6144;          // [9*64][20] (16 ic + pad)
    __half* gbuf_h = (__half*)sm;    // overlay: [256][66] halves
    float* wus = sm + 8448;          // overlay: [64][194]

    const int tid  = threadIdx.x;
    const int warp = tid >> 5, lane = tid & 31;
    const int gID  = lane >> 2, tig = lane & 3;
    const int b    = blockIdx.y;
    const int t    = blockIdx.x;          // 0..13
    const int row0 = (t % 7) * 8;
    const int col0 = (t / 7) * 24;        // {0, 24}; cols overlap 24-31

    float c[2][8][4];
    #pragma unroll
    for (int mtl = 0; mtl < 2; mtl++)
        #pragma unroll
        for (int nt = 0; nt < 8; nt++)
            #pragma unroll
            for (int j = 0; j < 4; j++) c[mtl][nt][j] = 0.f;

    for (int ci = 0; ci < 4; ci++) {
        __syncthreads();
        // stage halo input [10][34] x 16 ic, tf32-rounded
        for (int i = tid; i < 5440; i += 256) {
            int s = i % 340, ic = i / 340;
            int hr = s / 34, hc = s % 34;
            int gy = row0 - 1 + hr, gx = col0 - 1 + hc;
            float v = 0.f;
            if (gy >= 0 && gy < H_ && gx >= 0 && gx < W_)
                v = g_xp[(size_t)(b * D_ + ci * 16 + ic) * HW_ + gy * W_ + gx];
            hin[s * 18 + ic] = tf32r(v);
        }
        // stage weights Bw[(tap*64+oc)][ic], tf32-rounded
        for (int i = tid; i < 9216; i += 256) {
            int ic = i & 15, rest = i >> 4;     // rest = tap*64 + oc
            int oc = rest & 63, tap = rest >> 6;
            Bw[rest * 20 + ic] =
                tf32r(g_convw[(size_t)b * 36864 + oc * 576 + (ci * 16 + ic) * 9 + tap]);
        }
        __syncthreads();

        #pragma unroll
        for (int tap = 0; tap < 9; tap++) {
            const int dy = tap / 3, dx = tap % 3;
            #pragma unroll
            for (int ks = 0; ks < 2; ks++) {
                const int kk = ks * 8;
                float a[2][4];
                #pragma unroll
                for (int mtl = 0; mtl < 2; mtl++) {
                    const float* ap = hin +
                        ((gID + dy) * 34 + 4 * warp + 2 * mtl + dx) * 18 + kk + tig;
                    a[mtl][0] = ap[0];
                    a[mtl][1] = ap[18];
                    a[mtl][2] = ap[4];
                    a[mtl][3] = ap[22];
                }
                #pragma unroll
                for (int nt = 0; nt < 8; nt++) {
                    const float* bp = Bw + (tap * 64 + nt * 8 + gID) * 20 + kk + tig;
                    float b0 = bp[0], b1 = bp[4];
                    mma8(c[0][nt], a[0][0], a[0][1], a[0][2], a[0][3], b0, b1);
                    mma8(c[1][nt], a[1][0], a[1][1], a[1][2], a[1][3], b0, b1);
                }
            }
        }
    }
    __syncthreads();   // conv done; overlay gbuf/wus

    // load Wu transposed: wus[d*194 + c] = Wu[c*64 + d]
    for (int i = tid; i < 12416; i += 256) {
        int d = i / 194, cc = i % 194;
        if (cc < 192) wus[i] = Wu[cc * 64 + d];
    }
    // quickGELU -> gbuf half2
    #pragma unroll
    for (int mtl = 0; mtl < 2; mtl++) {
        int m0 = (2 * warp + mtl) * 16 + gID;   // (r=gID, c=2mt); m0+8 -> c=2mt+1
        #pragma unroll
        for (int nt = 0; nt < 8; nt++) {
            int oc = nt * 8 + tig * 2;
            *(__half2*)(gbuf_h + m0 * 66 + oc) =
                __floats2half2_rn(qgelu(c[mtl][nt][0]), qgelu(c[mtl][nt][1]));
            *(__half2*)(gbuf_h + (m0 + 8) * 66 + oc) =
                __floats2half2_rn(qgelu(c[mtl][nt][2]), qgelu(c[mtl][nt][3]));
        }
    }
    __syncthreads();

    // up-proj + residual: warp owns 32 positions (4 groups of 8);
    // lane owns channels c0..c0+5 (3 packed pairs)
    const int c0 = lane * 6;
    for (int grp = 0; grp < 4; grp++) {
        int pbase = warp * 32 + grp * 8;
        ull a[8][3];
        int nidx[8];
        #pragma unroll
        for (int q = 0; q < 8; q++) {
            int m = pbase + q;
            int gy = row0 + (m & 7), gx = col0 + (m >> 3);
            int n = b * HW_ + gy * W_ + gx;
            nidx[q] = n;
            const float* xr = x + (size_t)n * C_ + c0;
            a[q][0] = pk2(xr[0] + bu[c0],     xr[1] + bu[c0 + 1]);
            a[q][1] = pk2(xr[2] + bu[c0 + 2], xr[3] + bu[c0 + 3]);
            a[q][2] = pk2(xr[4] + bu[c0 + 4], xr[5] + bu[c0 + 5]);
        }
        #pragma unroll 4
        for (int d = 0; d < 64; d++) {
            ull wv0 = lds_u64(wus + d * 194 + c0);
            ull wv1 = lds_u64(wus + d * 194 + c0 + 2);
            ull wv2 = lds_u64(wus + d * 194 + c0 + 4);
            #pragma unroll
            for (int q = 0; q < 8; q++) {
                ull gd = dup2(__half2float(gbuf_h[(pbase + q) * 66 + d]));
                fma2(a[q][0], gd, wv0);
                fma2(a[q][1], gd, wv1);
                fma2(a[q][2], gd, wv2);
            }
        }
        #pragma unroll
        for (int q = 0; q < 8; q++) {
            float* orr = out + (size_t)nidx[q] * C_ + c0;
            float v0, v1;
            unpk2(a[q][0], v0, v1); orr[0] = v0; orr[1] = v1;
            unpk2(a[q][1], v0, v1); orr[2] = v0; orr[3] = v1;
            unpk2(a[q][2], v0, v1); orr[4] = v0; orr[5] = v1;
        }
    }
}

// ============================================================================
extern "C" void kernel_launch(void* const* d_in, const int* in_sizes, int n_in,
                              void* d_out, int out_size)
{
    const float* x  = (const float*)d_in[0];
    const float* W1 = (const float*)d_in[1];
    const float* b1 = (const float*)d_in[2];
    const float* W2 = (const float*)d_in[3];
    const float* b2 = (const float*)d_in[4];
    const float* mt = (const float*)d_in[5];
    const float* Wh = (const float*)d_in[6];
    const float* bh = (const float*)d_in[7];
    const float* Wd = (const float*)d_in[8];
    const float* bd = (const float*)d_in[9];
    const float* Wu = (const float*)d_in[10];
    const float* bu = (const float*)d_in[11];
    float* out = (float*)d_out;

    cudaFuncSetAttribute(k1, cudaFuncAttributeMaxDynamicSharedMemorySize, 84480);
    cudaFuncSetAttribute(k5, cudaFuncAttributeMaxDynamicSharedMemorySize, 83456);

    k1<<<dim3(25, 32), 256, 84480>>>(x, W1, b1, W2, b2, mt, Wd, bd);
    k2<<<256, 128>>>();
    k3a<<<dim3(8, 32), 256>>>();
    k3b<<<32, 64>>>();
    k4<<<144, 256>>>(Wh, bh);
    k5<<<dim3(14, 32), 256, 83456>>>(x, Wu, bu, out);
}

// round 8
// speedup vs baseline: 3.3474x; 1.3067x over previous
#include <cuda_runtime.h>
#include <cuda_fp16.h>
#include <math.h>
#include <stdint.h>

#define B_  32
#define H_  56
#define W_  56
#define C_  192
#define D_  64
#define M_  8
#define HW_ 3136
#define N_  (B_*HW_)

typedef unsigned long long ull;

// ---------------- device scratch (no allocations allowed) ----------------
__device__ float g_pf[(size_t)N_ * 64];           // [n][64]
__device__ float g_xp[(size_t)B_ * D_ * HW_];     // [b][d][hw]
__device__ float g_logits[(size_t)M_ * B_ * HW_]; // [m][b][hw]
__device__ float g_stats[M_ * B_ * 2];            // per (m,b): max, 1/sum
__device__ float g_part[B_ * 8 * 64];             // partial mwf
__device__ float g_mwf[B_ * D_];                  // [b][64]
__device__ float g_convw[(size_t)B_ * D_ * D_ * 9]; // [b][oc][ic][3][3]

__device__ __forceinline__ float qgelu(float v) {
    return v / (1.f + __expf(-1.702f * v));
}
__device__ __forceinline__ ull dup2(float v) {
    ull r; asm("mov.b64 %0, {%1, %1};" : "=l"(r) : "f"(v)); return r;
}
__device__ __forceinline__ void unpk2(ull v, float& lo, float& hi) {
    asm("mov.b64 {%0, %1}, %2;" : "=f"(lo), "=f"(hi) : "l"(v));
}
__device__ __forceinline__ void fma2(ull& d, ull a, ull b) {
    asm("fma.rn.f32x2 %0, %1, %2, %0;" : "+l"(d) : "l"(a), "l"(b));
}
__device__ __forceinline__ unsigned sptr(const void* p) {
    return (unsigned)__cvta_generic_to_shared(p);
}
__device__ __forceinline__ ull lds_u64(const float* p) {
    ull r; asm("ld.shared.u64 %0, [%1];" : "=l"(r) : "r"(sptr(p))); return r;
}
__device__ __forceinline__ float tf32r(float v) {
    float r; asm("cvt.rna.tf32.f32 %0, %1;" : "=f"(r) : "f"(v)); return r;
}
// mma.sync m16n8k8 tf32
__device__ __forceinline__ void mma8(float* c, float a0, float a1, float a2, float a3,
                                     float b0, float b1) {
    asm volatile(
        "mma.sync.aligned.m16n8k8.row.col.f32.tf32.tf32.f32 "
        "{%0,%1,%2,%3}, {%4,%5,%6,%7}, {%8,%9}, {%0,%1,%2,%3};"
        : "+f"(c[0]), "+f"(c[1]), "+f"(c[2]), "+f"(c[3])
        : "r"(__float_as_uint(a0)), "r"(__float_as_uint(a1)),
          "r"(__float_as_uint(a2)), "r"(__float_as_uint(a3)),
          "r"(__float_as_uint(b0)), "r"(__float_as_uint(b1)));
}
// mma.sync m16n8k16 f16 inputs, f32 accum
__device__ __forceinline__ void mma16h(float* c, uint32_t a0, uint32_t a1,
                                       uint32_t a2, uint32_t a3,
                                       uint32_t b0, uint32_t b1) {
    asm volatile(
        "mma.sync.aligned.m16n8k16.row.col.f32.f16.f16.f32 "
        "{%0,%1,%2,%3}, {%4,%5,%6,%7}, {%8,%9}, {%0,%1,%2,%3};"
        : "+f"(c[0]), "+f"(c[1]), "+f"(c[2]), "+f"(c[3])
        : "r"(a0), "r"(a1), "r"(a2), "r"(a3), "r"(b0), "r"(b1));
}

// ============================================================================
// K1: D[128 pos][128 out] = x[128][192] @ [W1|Wd]^T via mma.sync tf32 (single).
// ============================================================================
__global__ __launch_bounds__(256, 2) void k1(
    const float* __restrict__ x, const float* __restrict__ W1, const float* __restrict__ b1,
    const float* __restrict__ W2, const float* __restrict__ b2, const float* __restrict__ mtok,
    const float* __restrict__ Wd, const float* __restrict__ bd)
{
    extern __shared__ float sm[];
    float* Ah = sm, *Bh = sm + 4608;
    float* hs = sm, *xs = sm + 8448, *W2s = sm + 16896;
    __shared__ float mt_s[M_ * 64];

    const int tid   = threadIdx.x;
    const int warp  = tid >> 5, lane = tid & 31;
    const int gID   = lane >> 2, tig = lane & 3;
    const int b     = blockIdx.y;
    const int hw0   = blockIdx.x * 128;
    const int P     = min(128, HW_ - hw0);

    for (int i = tid; i < M_ * 64; i += 256) mt_s[i] = mtok[i];

    float c[16][4];
    #pragma unroll
    for (int nt = 0; nt < 16; nt++)
        #pragma unroll
        for (int j = 0; j < 4; j++) c[nt][j] = 0.f;

    const float* xb = x + (size_t)(b * HW_ + hw0) * C_;

    for (int ch = 0; ch < 6; ch++) {
        const int k0 = ch * 32;
        __syncthreads();
        for (int i = tid; i < 1024; i += 256) {
            int r = i >> 3, q = i & 7;
            float4 v = make_float4(0.f, 0.f, 0.f, 0.f);
            if (r < P) v = *(const float4*)(xb + (size_t)r * C_ + k0 + q * 4);
            v.x = tf32r(v.x); v.y = tf32r(v.y); v.z = tf32r(v.z); v.w = tf32r(v.w);
            *(float4*)(Ah + r * 36 + q * 4) = v;
        }
        for (int i = tid; i < 1024; i += 256) {
            int n = i >> 3, q = i & 7;
            const float* src = (n < 64) ? (W1 + n * C_) : (Wd + (n - 64) * C_);
            float4 v = *(const float4*)(src + k0 + q * 4);
            v.x = tf32r(v.x); v.y = tf32r(v.y); v.z = tf32r(v.z); v.w = tf32r(v.w);
            *(float4*)(Bh + n * 36 + q * 4) = v;
        }
        __syncthreads();

        const int arow0 = warp * 16 + gID;
        #pragma unroll
        for (int ks = 0; ks < 4; ks++) {
            const int kk = ks * 8;
            float a0 = Ah[arow0 * 36 + kk + tig];
            float a1 = Ah[(arow0 + 8) * 36 + kk + tig];
            float a2 = Ah[arow0 * 36 + kk + tig + 4];
            float a3 = Ah[(arow0 + 8) * 36 + kk + tig + 4];
            #pragma unroll
            for (int nt = 0; nt < 16; nt++) {
                const int bn = nt * 8 + gID;
                float b0 = Bh[bn * 36 + kk + tig];
                float b1 = Bh[bn * 36 + kk + tig + 4];
                mma8(c[nt], a0, a1, a2, a3, b0, b1);
            }
        }
    }
    __syncthreads();

    {
        const int p0 = warp * 16 + gID, p1 = p0 + 8;
        #pragma unroll
        for (int nt = 0; nt < 16; nt++) {
            const int n = nt * 8 + tig * 2;
            if (nt < 8) {
                float bia = b1[n], bib = b1[n + 1];
                hs[p0 * 66 + n]     = fmaxf(c[nt][0] + bia, 0.f);
                hs[p0 * 66 + n + 1] = fmaxf(c[nt][1] + bib, 0.f);
                hs[p1 * 66 + n]     = fmaxf(c[nt][2] + bia, 0.f);
                hs[p1 * 66 + n + 1] = fmaxf(c[nt][3] + bib, 0.f);
            } else {
                const int d = n - 64;
                float bia = bd[d], bib = bd[d + 1];
                xs[d * 132 + p0]       = qgelu(c[nt][0] + bia);
                xs[(d + 1) * 132 + p0] = qgelu(c[nt][1] + bib);
                xs[d * 132 + p1]       = qgelu(c[nt][2] + bia);
                xs[(d + 1) * 132 + p1] = qgelu(c[nt][3] + bib);
            }
        }
    }
    for (int i = tid; i < 4096; i += 256) {
        int o = i >> 6, kk = i & 63;
        W2s[kk * 66 + o] = W2[o * 64 + kk];
    }
    __syncthreads();

    {
        float* xpb = g_xp + (size_t)b * D_ * HW_ + hw0;
        for (int i = tid; i < 8192; i += 256) {
            int d = i >> 7, p = i & 127;
            if (p < P) xpb[(size_t)d * HW_ + p] = xs[d * 132 + p];
        }
    }

    const int tx = tid & 15, ty = tid >> 4;
    ull c2[8][2];
    #pragma unroll
    for (int i = 0; i < 8; i++) { c2[i][0] = 0ULL; c2[i][1] = 0ULL; }
    #pragma unroll 4
    for (int kk = 0; kk < 64; kk++) {
        ull bv0 = lds_u64(W2s + kk * 66 + tx * 4);
        ull bv1 = lds_u64(W2s + kk * 66 + tx * 4 + 2);
        #pragma unroll
        for (int i = 0; i < 8; i++) {
            ull ad = dup2(hs[(ty + 16 * i) * 66 + kk]);
            fma2(c2[i][0], ad, bv0);
            fma2(c2[i][1], ad, bv1);
        }
    }
    __syncthreads();

    #pragma unroll
    for (int j = 0; j < 2; j++) {
        int o = tx * 4 + 2 * j;
        float bia = b2[o], bib = b2[o + 1];
        #pragma unroll
        for (int i = 0; i < 8; i++) {
            int p = ty + 16 * i;
            float v0, v1; unpk2(c2[i][j], v0, v1);
            v0 += bia; v1 += bib;
            hs[p * 66 + o] = v0; hs[p * 66 + o + 1] = v1;
            if (p < P) {
                float2* dst = (float2*)(g_pf + (size_t)(b * HW_ + hw0 + p) * 64 + o);
                *dst = make_float2(v0, v1);
            }
        }
    }
    __syncthreads();

    #pragma unroll
    for (int q = 0; q < 4; q++) {
        int t = tid + 256 * q;
        int p = t & 127, m = t >> 7;
        float acc = 0.f;
        #pragma unroll 8
        for (int k = 0; k < 64; k++) acc = fmaf(hs[p * 66 + k], mt_s[m * 64 + k], acc);
        if (p < P) g_logits[(size_t)(m * B_ + b) * HW_ + hw0 + p] = acc;
    }
}

// ============================================================================
// K2: per-(m,b) softmax stats over 3136 positions
// ============================================================================
__global__ __launch_bounds__(128) void k2()
{
    int row = blockIdx.x;
    const float* l = g_logits + (size_t)row * HW_;
    __shared__ float red[128];
    int tid = threadIdx.x;

    float mx = -3.4e38f;
    for (int p = tid; p < HW_; p += 128) mx = fmaxf(mx, l[p]);
    red[tid] = mx; __syncthreads();
    for (int s = 64; s > 0; s >>= 1) {
        if (tid < s) red[tid] = fmaxf(red[tid], red[tid + s]);
        __syncthreads();
    }
    mx = red[0]; __syncthreads();

    float sum = 0.f;
    for (int p = tid; p < HW_; p += 128) sum += __expf(l[p] - mx);
    red[tid] = sum; __syncthreads();
    for (int s = 64; s > 0; s >>= 1) {
        if (tid < s) red[tid] += red[tid + s];
        __syncthreads();
    }
    if (tid == 0) { g_stats[row * 2] = mx; g_stats[row * 2 + 1] = 1.f / red[0]; }
}

// ============================================================================
// K3a: partial mwf over 392-position chunks. grid (8, 32)
// ============================================================================
__global__ __launch_bounds__(256) void k3a()
{
    const int chunk = blockIdx.x, b = blockIdx.y;
    const int tid = threadIdx.x;
    const int p0 = chunk * 392;
    __shared__ float ms[392];
    __shared__ float mxs[M_], izs[M_];
    __shared__ float red[4][64];

    if (tid < M_) {
        mxs[tid] = g_stats[(tid * B_ + b) * 2];
        izs[tid] = g_stats[(tid * B_ + b) * 2 + 1];
    }
    __syncthreads();

    for (int p = tid; p < 392; p += 256) {
        float s = 0.f;
        #pragma unroll
        for (int m = 0; m < M_; m++)
            s += __expf(g_logits[(size_t)(m * B_ + b) * HW_ + p0 + p] - mxs[m]) * izs[m];
        ms[p] = s;
    }
    __syncthreads();

    int k = tid & 63, g = tid >> 6;
    float acc = 0.f;
    const float* pfb = g_pf + (size_t)(b * HW_ + p0) * 64;
    for (int p = g; p < 392; p += 4)
        acc = fmaf(ms[p], pfb[(size_t)p * 64 + k], acc);
    red[g][k] = acc;
    __syncthreads();
    if (g == 0)
        g_part[(b * 8 + chunk) * 64 + k] = red[0][k] + red[1][k] + red[2][k] + red[3][k];
}

// K3b: reduce partials -> g_mwf
__global__ __launch_bounds__(64) void k3b()
{
    int b = blockIdx.x, k = threadIdx.x;
    float acc = 0.f;
    #pragma unroll
    for (int c = 0; c < 8; c++) acc += g_part[(b * 8 + c) * 64 + k];
    g_mwf[b * 64 + k] = acc;
}

// ============================================================================
// K4: conv_w[b,o] = mwf[b] . Wh[o] + bh[o]
// ============================================================================
__global__ __launch_bounds__(256) void k4(const float* __restrict__ Wh,
                                          const float* __restrict__ bh)
{
    __shared__ float ms[2048];
    int tid = threadIdx.x;
    for (int i = tid; i < 2048; i += 256) ms[i] = g_mwf[i];
    __syncthreads();

    int o = blockIdx.x * 256 + tid;
    float4 wv[16];
    const float4* wr = (const float4*)(Wh + (size_t)o * 64);
    #pragma unroll
    for (int i = 0; i < 16; i++) wv[i] = wr[i];
    const float* wf = (const float*)wv;
    float bias = bh[o];

    for (int b = 0; b < B_; b++) {
        float acc = bias;
        const float* mb = ms + b * 64;
        #pragma unroll
        for (int kk = 0; kk < 64; kk++) acc = fmaf(mb[kk], wf[kk], acc);
        g_convw[(size_t)b * 36864 + o] = acc;
    }
}

// ============================================================================
// K5: conv (tf32 mma) + quickGELU (half smem) + up-proj (f16 mma) + residual.
// tile 8 rows x 32 cols = 256 positions (m = c*8+r), 256 threads, 2 blocks/SM.
// ============================================================================
__global__ __launch_bounds__(256, 2) void k5(const float* __restrict__ x,
                                             const float* __restrict__ Wu,
                                             const float* __restrict__ bu,
                                             float* __restrict__ out)
{
    extern __shared__ float sm[];
    float* hin = sm;                 // [340 spatial][18]
    float* Bw  = sm + 6144;          // [9*64][20]
    __half* gbuf = (__half*)sm;      // overlay: [256 m][72] halves (36864 B)
    __half* wuh  = (__half*)sm + 18432; // overlay: [192 n][72] halves (27648 B)
    __shared__ float bus[C_];

    const int tid  = threadIdx.x;
    const int warp = tid >> 5, lane = tid & 31;
    const int gID  = lane >> 2, tig = lane & 3;
    const int b    = blockIdx.y;
    const int t    = blockIdx.x;          // 0..13
    const int row0 = (t % 7) * 8;
    const int col0 = (t / 7) * 24;        // {0, 24}; cols overlap (benign dup)

    for (int i = tid; i < C_; i += 256) bus[i] = bu[i];

    float c[2][8][4];
    #pragma unroll
    for (int mtl = 0; mtl < 2; mtl++)
        #pragma unroll
        for (int nt = 0; nt < 8; nt++)
            #pragma unroll
            for (int j = 0; j < 4; j++) c[mtl][nt][j] = 0.f;

    for (int ci = 0; ci < 4; ci++) {
        __syncthreads();
        for (int i = tid; i < 5440; i += 256) {
            int s = i % 340, ic = i / 340;
            int hr = s / 34, hc = s % 34;
            int gy = row0 - 1 + hr, gx = col0 - 1 + hc;
            float v = 0.f;
            if (gy >= 0 && gy < H_ && gx >= 0 && gx < W_)
                v = g_xp[(size_t)(b * D_ + ci * 16 + ic) * HW_ + gy * W_ + gx];
            hin[s * 18 + ic] = tf32r(v);
        }
        for (int i = tid; i < 9216; i += 256) {
            int ic = i & 15, rest = i >> 4;
            int oc = rest & 63, tap = rest >> 6;
            Bw[rest * 20 + ic] =
                tf32r(g_convw[(size_t)b * 36864 + oc * 576 + (ci * 16 + ic) * 9 + tap]);
        }
        __syncthreads();

        #pragma unroll
        for (int tap = 0; tap < 9; tap++) {
            const int dy = tap / 3, dx = tap % 3;
            #pragma unroll
            for (int ks = 0; ks < 2; ks++) {
                const int kk = ks * 8;
                float a[2][4];
                #pragma unroll
                for (int mtl = 0; mtl < 2; mtl++) {
                    const float* ap = hin +
                        ((gID + dy) * 34 + 4 * warp + 2 * mtl + dx) * 18 + kk + tig;
                    a[mtl][0] = ap[0];
                    a[mtl][1] = ap[18];
                    a[mtl][2] = ap[4];
                    a[mtl][3] = ap[22];
                }
                #pragma unroll
                for (int nt = 0; nt < 8; nt++) {
                    const float* bp = Bw + (tap * 64 + nt * 8 + gID) * 20 + kk + tig;
                    float b0 = bp[0], b1 = bp[4];
                    mma8(c[0][nt], a[0][0], a[0][1], a[0][2], a[0][3], b0, b1);
                    mma8(c[1][nt], a[1][0], a[1][1], a[1][2], a[1][3], b0, b1);
                }
            }
        }
    }
    __syncthreads();   // conv done; overlay gbuf/wuh

    // quickGELU -> gbuf half2, stride 72
    #pragma unroll
    for (int mtl = 0; mtl < 2; mtl++) {
        int m0 = (2 * warp + mtl) * 16 + gID;
        #pragma unroll
        for (int nt = 0; nt < 8; nt++) {
            int oc = nt * 8 + tig * 2;
            *(__half2*)(gbuf + m0 * 72 + oc) =
                __floats2half2_rn(qgelu(c[mtl][nt][0]), qgelu(c[mtl][nt][1]));
            *(__half2*)(gbuf + (m0 + 8) * 72 + oc) =
                __floats2half2_rn(qgelu(c[mtl][nt][2]), qgelu(c[mtl][nt][3]));
        }
    }
    // stage Wu as half: wuh[n][k] = Wu[n*64+k]  (row-major already matches)
    for (int i = tid; i < 12288; i += 256) {
        int n = i >> 6, k = i & 63;
        wuh[n * 72 + k] = __float2half_rn(Wu[i]);
    }
    __syncthreads();

    // up-proj: D[256 pos][192 ch] = gbuf @ wuh^T via f16 mma, 3 passes of 64 ch
    for (int pass = 0; pass < 3; pass++) {
        float cc[2][8][4];
        #pragma unroll
        for (int mtl = 0; mtl < 2; mtl++)
            #pragma unroll
            for (int nt = 0; nt < 8; nt++)
                #pragma unroll
                for (int j = 0; j < 4; j++) cc[mtl][nt][j] = 0.f;

        #pragma unroll
        for (int ks = 0; ks < 4; ks++) {
            const int k0 = ks * 16;
            uint32_t a[2][4];
            #pragma unroll
            for (int mtl = 0; mtl < 2; mtl++) {
                int r0 = (warp * 2 + mtl) * 16 + gID;
                const __half* g0 = gbuf + r0 * 72 + k0 + tig * 2;
                a[mtl][0] = *(const uint32_t*)(g0);
                a[mtl][1] = *(const uint32_t*)(g0 + 8 * 72);
                a[mtl][2] = *(const uint32_t*)(g0 + 8);
                a[mtl][3] = *(const uint32_t*)(g0 + 8 * 72 + 8);
            }
            #pragma unroll
            for (int nt = 0; nt < 8; nt++) {
                const __half* w0 = wuh + (pass * 64 + nt * 8 + gID) * 72 + k0 + tig * 2;
                uint32_t b0 = *(const uint32_t*)(w0);
                uint32_t b1 = *(const uint32_t*)(w0 + 8);
                mma16h(cc[0][nt], a[0][0], a[0][1], a[0][2], a[0][3], b0, b1);
                mma16h(cc[1][nt], a[1][0], a[1][1], a[1][2], a[1][3], b0, b1);
            }
        }
        // epilogue: residual + bias, direct float2 stores
        #pragma unroll
        for (int mtl = 0; mtl < 2; mtl++) {
            #pragma unroll
            for (int hf = 0; hf < 2; hf++) {
                int m = (warp * 2 + mtl) * 16 + gID + hf * 8;
                int gy = row0 + (m & 7), gx = col0 + (m >> 3);
                size_t n = (size_t)b * HW_ + gy * W_ + gx;
                const float* xr = x + n * C_;
                float* orr = out + n * C_;
                #pragma unroll
                for (int nt = 0; nt < 8; nt++) {
                    int chn = pass * 64 + nt * 8 + tig * 2;
                    float2 xv = *(const float2*)(xr + chn);
                    float v0 = cc[mtl][nt][hf * 2 + 0] + bus[chn]     + xv.x;
                    float v1 = cc[mtl][nt][hf * 2 + 1] + bus[chn + 1] + xv.y;
                    *(float2*)(orr + chn) = make_float2(v0, v1);
                }
            }
        }
    }
}

// ============================================================================
extern "C" void kernel_launch(void* const* d_in, const int* in_sizes, int n_in,
                              void* d_out, int out_size)
{
    const float* x  = (const float*)d_in[0];
    const float* W1 = (const float*)d_in[1];
    const float* b1 = (const float*)d_in[2];
    const float* W2 = (const float*)d_in[3];
    const float* b2 = (const float*)d_in[4];
    const float* mt = (const float*)d_in[5];
    const float* Wh = (const float*)d_in[6];
    const float* bh = (const float*)d_in[7];
    const float* Wd = (const float*)d_in[8];
    const float* bd = (const float*)d_in[9];
    const float* Wu = (const float*)d_in[10];
    const float* bu = (const float*)d_in[11];
    float* out = (float*)d_out;

    cudaFuncSetAttribute(k1, cudaFuncAttributeMaxDynamicSharedMemorySize, 84480);
    cudaFuncSetAttribute(k5, cudaFuncAttributeMaxDynamicSharedMemorySize, 70656);

    k1<<<dim3(25, 32), 256, 84480>>>(x, W1, b1, W2, b2, mt, Wd, bd);
    k2<<<256, 128>>>();
    k3a<<<dim3(8, 32), 256>>>();
    k3b<<<32, 64>>>();
    k4<<<144, 256>>>(Wh, bh);
    k5<<<dim3(14, 32), 256, 70656>>>(x, Wu, bu, out);
}

// round 10
// speedup vs baseline: 3.9376x; 1.1763x over previous
#include <cuda_runtime.h>
#include <cuda_fp16.h>
#include <math.h>
#include <stdint.h>

#define B_  32
#define H_  56
#define W_  56
#define C_  192
#define D_  64
#define M_  8
#define HW_ 3136
#define N_  (B_*HW_)

// ---------------- device scratch (no allocations allowed) ----------------
__device__ float  g_pf[(size_t)N_ * 64];            // [n][64]
__device__ __half g_xp[(size_t)B_ * D_ * HW_];      // [b][d][hw] half
__device__ float  g_logits[(size_t)M_ * B_ * HW_];  // [m][b][hw]
__device__ float  g_stats[M_ * B_ * 2];             // per (m,b): max, 1/sum
__device__ float  g_part[B_ * 8 * 64];              // partial mwf
__device__ float  g_convw[(size_t)B_ * D_ * D_ * 9];// [b][oc][ic][3][3]

__device__ __forceinline__ float qgelu(float v) {
    return v / (1.f + __expf(-1.702f * v));
}
__device__ __forceinline__ float tf32r(float v) {
    float r; asm("cvt.rna.tf32.f32 %0, %1;" : "=f"(r) : "f"(v)); return r;
}
// mma.sync m16n8k8 tf32
__device__ __forceinline__ void mma8(float* c, float a0, float a1, float a2, float a3,
                                     float b0, float b1) {
    asm volatile(
        "mma.sync.aligned.m16n8k8.row.col.f32.tf32.tf32.f32 "
        "{%0,%1,%2,%3}, {%4,%5,%6,%7}, {%8,%9}, {%0,%1,%2,%3};"
        : "+f"(c[0]), "+f"(c[1]), "+f"(c[2]), "+f"(c[3])
        : "r"(__float_as_uint(a0)), "r"(__float_as_uint(a1)),
          "r"(__float_as_uint(a2)), "r"(__float_as_uint(a3)),
          "r"(__float_as_uint(b0)), "r"(__float_as_uint(b1)));
}
// mma.sync m16n8k16 f16 inputs, f32 accum
__device__ __forceinline__ void mma16h(float* c, uint32_t a0, uint32_t a1,
                                       uint32_t a2, uint32_t a3,
                                       uint32_t b0, uint32_t b1) {
    asm volatile(
        "mma.sync.aligned.m16n8k16.row.col.f32.f16.f16.f32 "
        "{%0,%1,%2,%3}, {%4,%5,%6,%7}, {%8,%9}, {%0,%1,%2,%3};"
        : "+f"(c[0]), "+f"(c[1]), "+f"(c[2]), "+f"(c[3])
        : "r"(a0), "r"(a1), "r"(a2), "r"(a3), "r"(b0), "r"(b1));
}

// ============================================================================
// K1: main GEMM (tf32 mma) -> relu/gelu; pf = hs@W2^T (tf32 mma);
//     logits = pf @ mask^T (tf32 mma). 256 threads, 2 blocks/SM.
// ============================================================================
__global__ __launch_bounds__(256, 2) void k1(
    const float* __restrict__ x, const float* __restrict__ W1, const float* __restrict__ b1,
    const float* __restrict__ W2, const float* __restrict__ b2, const float* __restrict__ mtok,
    const float* __restrict__ Wd, const float* __restrict__ bd)
{
    extern __shared__ float sm[];
    // phase1: Ah@0 [128*36], Bh@4608 [128*36]
    float* Ah = sm, *Bh = sm + 4608;
    // phase2: hs@0 [128*68]; xsh(half)@8704 [64*132]; W2s@12928 [64*68]
    float* hs = sm;
    __half* xsh = (__half*)(sm + 8704);
    float* W2s = sm + 12928;
    __shared__ float mt_s[M_ * 68];

    const int tid   = threadIdx.x;
    const int warp  = tid >> 5, lane = tid & 31;
    const int gID   = lane >> 2, tig = lane & 3;
    const int b     = blockIdx.y;
    const int hw0   = blockIdx.x * 128;
    const int P     = min(128, HW_ - hw0);

    for (int i = tid; i < 512; i += 256) {
        int m = i >> 6, k = i & 63;
        mt_s[m * 68 + k] = tf32r(mtok[m * 64 + k]);
    }

    float c[16][4];
    #pragma unroll
    for (int nt = 0; nt < 16; nt++)
        #pragma unroll
        for (int j = 0; j < 4; j++) c[nt][j] = 0.f;

    const float* xb = x + (size_t)(b * HW_ + hw0) * C_;

    for (int ch = 0; ch < 6; ch++) {
        const int k0 = ch * 32;
        __syncthreads();
        for (int i = tid; i < 1024; i += 256) {
            int r = i >> 3, q = i & 7;
            float4 v = make_float4(0.f, 0.f, 0.f, 0.f);
            if (r < P) v = *(const float4*)(xb + (size_t)r * C_ + k0 + q * 4);
            v.x = tf32r(v.x); v.y = tf32r(v.y); v.z = tf32r(v.z); v.w = tf32r(v.w);
            *(float4*)(Ah + r * 36 + q * 4) = v;
        }
        for (int i = tid; i < 1024; i += 256) {
            int n = i >> 3, q = i & 7;
            const float* src = (n < 64) ? (W1 + n * C_) : (Wd + (n - 64) * C_);
            float4 v = *(const float4*)(src + k0 + q * 4);
            v.x = tf32r(v.x); v.y = tf32r(v.y); v.z = tf32r(v.z); v.w = tf32r(v.w);
            *(float4*)(Bh + n * 36 + q * 4) = v;
        }
        __syncthreads();

        const int arow0 = warp * 16 + gID;
        #pragma unroll
        for (int ks = 0; ks < 4; ks++) {
            const int kk = ks * 8;
            float a0 = Ah[arow0 * 36 + kk + tig];
            float a1 = Ah[(arow0 + 8) * 36 + kk + tig];
            float a2 = Ah[arow0 * 36 + kk + tig + 4];
            float a3 = Ah[(arow0 + 8) * 36 + kk + tig + 4];
            #pragma unroll
            for (int nt = 0; nt < 16; nt++) {
                const int bn = nt * 8 + gID;
                float b0 = Bh[bn * 36 + kk + tig];
                float b1 = Bh[bn * 36 + kk + tig + 4];
                mma8(c[nt], a0, a1, a2, a3, b0, b1);
            }
        }
    }
    __syncthreads();   // staging dead; overlay hs/xsh/W2s

    // epilogue: cols 0-63 relu -> hs (tf32-rounded); 64-127 qgelu -> xsh half
    {
        const int p0 = warp * 16 + gID, p1 = p0 + 8;
        #pragma unroll
        for (int nt = 0; nt < 16; nt++) {
            const int n = nt * 8 + tig * 2;
            if (nt < 8) {
                float bia = b1[n], bib = b1[n + 1];
                hs[p0 * 68 + n]     = tf32r(fmaxf(c[nt][0] + bia, 0.f));
                hs[p0 * 68 + n + 1] = tf32r(fmaxf(c[nt][1] + bib, 0.f));
                hs[p1 * 68 + n]     = tf32r(fmaxf(c[nt][2] + bia, 0.f));
                hs[p1 * 68 + n + 1] = tf32r(fmaxf(c[nt][3] + bib, 0.f));
            } else {
                const int d = n - 64;
                float bia = bd[d], bib = bd[d + 1];
                xsh[d * 132 + p0]       = __float2half_rn(qgelu(c[nt][0] + bia));
                xsh[(d + 1) * 132 + p0] = __float2half_rn(qgelu(c[nt][1] + bib));
                xsh[d * 132 + p1]       = __float2half_rn(qgelu(c[nt][2] + bia));
                xsh[(d + 1) * 132 + p1] = __float2half_rn(qgelu(c[nt][3] + bib));
            }
        }
    }
    // stage W2s tf32 [o][k] stride 68
    for (int i = tid; i < 4096; i += 256) {
        int o = i >> 6, kk = i & 63;
        W2s[o * 68 + kk] = tf32r(W2[i]);
    }
    __syncthreads();

    // coalesced g_xp write (half2)
    {
        __half2* xpb = (__half2*)(g_xp + (size_t)b * D_ * HW_ + hw0);
        for (int i = tid; i < 4096; i += 256) {
            int d = i >> 6, pp = i & 63;
            int p = pp * 2;
            if (p < P) {
                __half2 v = __halves2half2(xsh[d * 132 + p], xsh[d * 132 + p + 1]);
                xpb[(size_t)d * (HW_ / 2) + pp] = v;
            }
        }
    }

    // pf = hs @ W2^T via tf32 mma: M=128, N=64, K=64
    float cc[8][4];
    #pragma unroll
    for (int nt = 0; nt < 8; nt++)
        #pragma unroll
        for (int j = 0; j < 4; j++) cc[nt][j] = 0.f;
    {
        const int arow0 = warp * 16 + gID;
        #pragma unroll
        for (int ks = 0; ks < 8; ks++) {
            const int kk = ks * 8;
            float a0 = hs[arow0 * 68 + kk + tig];
            float a1 = hs[(arow0 + 8) * 68 + kk + tig];
            float a2 = hs[arow0 * 68 + kk + tig + 4];
            float a3 = hs[(arow0 + 8) * 68 + kk + tig + 4];
            #pragma unroll
            for (int nt = 0; nt < 8; nt++) {
                const int bn = nt * 8 + gID;
                float b0 = W2s[bn * 68 + kk + tig];
                float b1 = W2s[bn * 68 + kk + tig + 4];
                mma8(cc[nt], a0, a1, a2, a3, b0, b1);
            }
        }
    }
    __syncthreads();   // all pf reads of hs done before overwrite

    // write pf: hs (tf32-rounded, for logits mma) + g_pf (float2)
    {
        const int p0 = warp * 16 + gID, p1 = p0 + 8;
        #pragma unroll
        for (int nt = 0; nt < 8; nt++) {
            const int n = nt * 8 + tig * 2;
            float bia = b2[n], bib = b2[n + 1];
            float v00 = cc[nt][0] + bia, v01 = cc[nt][1] + bib;
            float v10 = cc[nt][2] + bia, v11 = cc[nt][3] + bib;
            hs[p0 * 68 + n]     = tf32r(v00);
            hs[p0 * 68 + n + 1] = tf32r(v01);
            hs[p1 * 68 + n]     = tf32r(v10);
            hs[p1 * 68 + n + 1] = tf32r(v11);
            if (p0 < P)
                *(float2*)(g_pf + (size_t)(b * HW_ + hw0 + p0) * 64 + n) = make_float2(v00, v01);
            if (p1 < P)
                *(float2*)(g_pf + (size_t)(b * HW_ + hw0 + p1) * 64 + n) = make_float2(v10, v11);
        }
    }
    __syncthreads();

    // logits = pf @ mask^T via tf32 mma: M=128, N=8, K=64
    {
        float cl[4] = {0.f, 0.f, 0.f, 0.f};
        const int arow0 = warp * 16 + gID;
        #pragma unroll
        for (int ks = 0; ks < 8; ks++) {
            const int kk = ks * 8;
            float a0 = hs[arow0 * 68 + kk + tig];
            float a1 = hs[(arow0 + 8) * 68 + kk + tig];
            float a2 = hs[arow0 * 68 + kk + tig + 4];
            float a3 = hs[(arow0 + 8) * 68 + kk + tig + 4];
            float b0 = mt_s[gID * 68 + kk + tig];
            float b1 = mt_s[gID * 68 + kk + tig + 4];
            mma8(cl, a0, a1, a2, a3, b0, b1);
        }
        const int p0 = warp * 16 + gID, p1 = p0 + 8;
        const int m0 = tig * 2, m1 = tig * 2 + 1;
        if (p0 < P) {
            g_logits[(size_t)(m0 * B_ + b) * HW_ + hw0 + p0] = cl[0];
            g_logits[(size_t)(m1 * B_ + b) * HW_ + hw0 + p0] = cl[1];
        }
        if (p1 < P) {
            g_logits[(size_t)(m0 * B_ + b) * HW_ + hw0 + p1] = cl[2];
            g_logits[(size_t)(m1 * B_ + b) * HW_ + hw0 + p1] = cl[3];
        }
    }
}

// ============================================================================
// K2: per-(m,b) softmax stats over 3136 positions
// ============================================================================
__global__ __launch_bounds__(128) void k2()
{
    int row = blockIdx.x;
    const float* l = g_logits + (size_t)row * HW_;
    __shared__ float red[128];
    int tid = threadIdx.x;

    float mx = -3.4e38f;
    for (int p = tid; p < HW_; p += 128) mx = fmaxf(mx, l[p]);
    red[tid] = mx; __syncthreads();
    for (int s = 64; s > 0; s >>= 1) {
        if (tid < s) red[tid] = fmaxf(red[tid], red[tid + s]);
        __syncthreads();
    }
    mx = red[0]; __syncthreads();

    float sum = 0.f;
    for (int p = tid; p < HW_; p += 128) sum += __expf(l[p] - mx);
    red[tid] = sum; __syncthreads();
    for (int s = 64; s > 0; s >>= 1) {
        if (tid < s) red[tid] += red[tid + s];
        __syncthreads();
    }
    if (tid == 0) { g_stats[row * 2] = mx; g_stats[row * 2 + 1] = 1.f / red[0]; }
}

// ============================================================================
// K3a: partial mwf over 392-position chunks. grid (8, 32)
// ============================================================================
__global__ __launch_bounds__(256) void k3a()
{
    const int chunk = blockIdx.x, b = blockIdx.y;
    const int tid = threadIdx.x;
    const int p0 = chunk * 392;
    __shared__ float ms[392];
    __shared__ float mxs[M_], izs[M_];
    __shared__ float red[4][64];

    if (tid < M_) {
        mxs[tid] = g_stats[(tid * B_ + b) * 2];
        izs[tid] = g_stats[(tid * B_ + b) * 2 + 1];
    }
    __syncthreads();

    for (int p = tid; p < 392; p += 256) {
        float s = 0.f;
        #pragma unroll
        for (int m = 0; m < M_; m++)
            s += __expf(g_logits[(size_t)(m * B_ + b) * HW_ + p0 + p] - mxs[m]) * izs[m];
        ms[p] = s;
    }
    __syncthreads();

    int k = tid & 63, g = tid >> 6;
    float acc = 0.f;
    const float* pfb = g_pf + (size_t)(b * HW_ + p0) * 64;
    for (int p = g; p < 392; p += 4)
        acc = fmaf(ms[p], pfb[(size_t)p * 64 + k], acc);
    red[g][k] = acc;
    __syncthreads();
    if (g == 0)
        g_part[(b * 8 + chunk) * 64 + k] = red[0][k] + red[1][k] + red[2][k] + red[3][k];
}

// ============================================================================
// K4: reduce g_part -> mwf (smem), then conv_w[b,o] = mwf[b].Wh[o] + bh[o]
// ============================================================================
__global__ __launch_bounds__(256) void k4(const float* __restrict__ Wh,
                                          const float* __restrict__ bh)
{
    __shared__ float ms[2048];
    int tid = threadIdx.x;
    for (int i = tid; i < 2048; i += 256) {
        int bb = i >> 6, k = i & 63;
        float acc = 0.f;
        #pragma unroll
        for (int cch = 0; cch < 8; cch++) acc += g_part[(bb * 8 + cch) * 64 + k];
        ms[i] = acc;
    }
    __syncthreads();

    int o = blockIdx.x * 256 + tid;
    float4 wv[16];
    const float4* wr = (const float4*)(Wh + (size_t)o * 64);
    #pragma unroll
    for (int i = 0; i < 16; i++) wv[i] = wr[i];
    const float* wf = (const float*)wv;
    float bias = bh[o];

    for (int b = 0; b < B_; b++) {
        float acc = bias;
        const float* mb = ms + b * 64;
        #pragma unroll
        for (int kk = 0; kk < 64; kk++) acc = fmaf(mb[kk], wf[kk], acc);
        g_convw[(size_t)b * 36864 + o] = acc;
    }
}

// ============================================================================
// K5: conv (f16 m16n8k16 mma) + quickGELU + up-proj (f16 mma) + residual.
// tile 8 rows x 32 cols = 256 positions (m = c*8+r), 256 threads, 2 blocks/SM.
// ============================================================================
__global__ __launch_bounds__(256, 2) void k5(const float* __restrict__ x,
                                             const float* __restrict__ Wu,
                                             const float* __restrict__ bu,
                                             float* __restrict__ out)
{
    extern __shared__ float sm[];
    __half* hbase = (__half*)sm;
    __half* hin_h = hbase;             // [340 spatial][20] halves (13600 B)
    __half* Bw_h  = hbase + 6800;      // [576][24] halves (27648 B)
    __half* gbuf  = hbase;             // overlay: [256 m][72] halves (36864 B)
    __half* wuh   = hbase + 18432;     // overlay: [192 n][72] halves (27648 B)
    __shared__ float bus[C_];

    const int tid  = threadIdx.x;
    const int warp = tid >> 5, lane = tid & 31;
    const int gID  = lane >> 2, tig = lane & 3;
    const int b    = blockIdx.y;
    const int t    = blockIdx.x;          // 0..13
    const int row0 = (t % 7) * 8;
    const int col0 = (t / 7) * 24;        // {0, 24}; cols overlap (benign dup)

    for (int i = tid; i < C_; i += 256) bus[i] = bu[i];

    float c[2][8][4];
    #pragma unroll
    for (int mtl = 0; mtl < 2; mtl++)
        #pragma unroll
        for (int nt = 0; nt < 8; nt++)
            #pragma unroll
            for (int j = 0; j < 4; j++) c[mtl][nt][j] = 0.f;

    for (int ci = 0; ci < 4; ci++) {
        __syncthreads();
        // stage halo input [10][34] x 16 ic (half2 per ic-pair)
        for (int i = tid; i < 2720; i += 256) {
            int s = i >> 3, jc = i & 7;
            int hr = s / 34, hc = s % 34;
            int gy = row0 - 1 + hr, gx = col0 - 1 + hc;
            __half2 v = __halves2half2(__float2half(0.f), __float2half(0.f));
            if (gy >= 0 && gy < H_ && gx >= 0 && gx < W_) {
                size_t base = (size_t)(b * D_ + ci * 16 + 2 * jc) * HW_ + gy * W_ + gx;
                v = __halves2half2(g_xp[base], g_xp[base + HW_]);
            }
            *(__half2*)(hin_h + s * 20 + 2 * jc) = v;
        }
        // stage weights Bw_h[(tap*64+oc)][ic] halves
        for (int i = tid; i < 9216; i += 256) {
            int ic = i & 15, rest = i >> 4;
            int oc = rest & 63, tap = rest >> 6;
            Bw_h[rest * 24 + ic] =
                __float2half_rn(g_convw[(size_t)b * 36864 + oc * 576 + (ci * 16 + ic) * 9 + tap]);
        }
        __syncthreads();

        #pragma unroll
        for (int tap = 0; tap < 9; tap++) {
            const int dy = tap / 3, dx = tap % 3;
            uint32_t a[2][4];
            #pragma unroll
            for (int mtl = 0; mtl < 2; mtl++) {
                const __half* ap = hin_h +
                    ((gID + dy) * 34 + 4 * warp + 2 * mtl + dx) * 20 + 2 * tig;
                a[mtl][0] = *(const uint32_t*)(ap);
                a[mtl][1] = *(const uint32_t*)(ap + 20);   // m+8 (next spatial col)
                a[mtl][2] = *(const uint32_t*)(ap + 8);    // k+8
                a[mtl][3] = *(const uint32_t*)(ap + 28);
            }
            #pragma unroll
            for (int nt = 0; nt < 8; nt++) {
                const __half* bp = Bw_h + (tap * 64 + nt * 8 + gID) * 24 + 2 * tig;
                uint32_t b0 = *(const uint32_t*)(bp);
                uint32_t b1 = *(const uint32_t*)(bp + 8);
                mma16h(c[0][nt], a[0][0], a[0][1], a[0][2], a[0][3], b0, b1);
                mma16h(c[1][nt], a[1][0], a[1][1], a[1][2], a[1][3], b0, b1);
            }
        }
    }
    __syncthreads();   // conv done; overlay gbuf/wuh

    // quickGELU -> gbuf half2, stride 72
    #pragma unroll
    for (int mtl = 0; mtl < 2; mtl++) {
        int m0 = (2 * warp + mtl) * 16 + gID;
        #pragma unroll
        for (int nt = 0; nt < 8; nt++) {
            int oc = nt * 8 + tig * 2;
            *(__half2*)(gbuf + m0 * 72 + oc) =
                __floats2half2_rn(qgelu(c[mtl][nt][0]), qgelu(c[mtl][nt][1]));
            *(__half2*)(gbuf + (m0 + 8) * 72 + oc) =
                __floats2half2_rn(qgelu(c[mtl][nt][2]), qgelu(c[mtl][nt][3]));
        }
    }
    // stage Wu as half: wuh[n][k]
    for (int i = tid; i < 12288; i += 256) {
        int n = i >> 6, k = i & 63;
        wuh[n * 72 + k] = __float2half_rn(Wu[i]);
    }
    __syncthreads();

    // up-proj: D[256 pos][192 ch] = gbuf @ wuh^T via f16 mma, 3 passes of 64 ch
    for (int pass = 0; pass < 3; pass++) {
        float cc[2][8][4];
        #pragma unroll
        for (int mtl = 0; mtl < 2; mtl++)
            #pragma unroll
            for (int nt = 0; nt < 8; nt++)
                #pragma unroll
                for (int j = 0; j < 4; j++) cc[mtl][nt][j] = 0.f;

        #pragma unroll
        for (int ks = 0; ks < 4; ks++) {
            const int k0 = ks * 16;
            uint32_t a[2][4];
            #pragma unroll
            for (int mtl = 0; mtl < 2; mtl++) {
                int r0 = (warp * 2 + mtl) * 16 + gID;
                const __half* g0 = gbuf + r0 * 72 + k0 + tig * 2;
                a[mtl][0] = *(const uint32_t*)(g0);
                a[mtl][1] = *(const uint32_t*)(g0 + 8 * 72);
                a[mtl][2] = *(const uint32_t*)(g0 + 8);
                a[mtl][3] = *(const uint32_t*)(g0 + 8 * 72 + 8);
            }
            #pragma unroll
            for (int nt = 0; nt < 8; nt++) {
                const __half* w0 = wuh + (pass * 64 + nt * 8 + gID) * 72 + k0 + tig * 2;
                uint32_t b0 = *(const uint32_t*)(w0);
                uint32_t b1 = *(const uint32_t*)(w0 + 8);
                mma16h(cc[0][nt], a[0][0], a[0][1], a[0][2], a[0][3], b0, b1);
                mma16h(cc[1][nt], a[1][0], a[1][1], a[1][2], a[1][3], b0, b1);
            }
        }
        // epilogue: residual + bias, direct float2 stores
        #pragma unroll
        for (int mtl = 0; mtl < 2; mtl++) {
            #pragma unroll
            for (int hf = 0; hf < 2; hf++) {
                int m = (warp * 2 + mtl) * 16 + gID + hf * 8;
                int gy = row0 + (m & 7), gx = col0 + (m >> 3);
                size_t n = (size_t)b * HW_ + gy * W_ + gx;
                const float* xr = x + n * C_;
                float* orr = out + n * C_;
                #pragma unroll
                for (int nt = 0; nt < 8; nt++) {
                    int chn = pass * 64 + nt * 8 + tig * 2;
                    float2 xv = *(const float2*)(xr + chn);
                    float v0 = cc[mtl][nt][hf * 2 + 0] + bus[chn]     + xv.x;
                    float v1 = cc[mtl][nt][hf * 2 + 1] + bus[chn + 1] + xv.y;
                    *(float2*)(orr + chn) = make_float2(v0, v1);
                }
            }
        }
    }
}

// ============================================================================
extern "C" void kernel_launch(void* const* d_in, const int* in_sizes, int n_in,
                              void* d_out, int out_size)
{
    const float* x  = (const float*)d_in[0];
    const float* W1 = (const float*)d_in[1];
    const float* b1 = (const float*)d_in[2];
    const float* W2 = (const float*)d_in[3];
    const float* b2 = (const float*)d_in[4];
    const float* mt = (const float*)d_in[5];
    const float* Wh = (const float*)d_in[6];
    const float* bh = (const float*)d_in[7];
    const float* Wd = (const float*)d_in[8];
    const float* bd = (const float*)d_in[9];
    const float* Wu = (const float*)d_in[10];
    const float* bu = (const float*)d_in[11];
    float* out = (float*)d_out;

    cudaFuncSetAttribute(k1, cudaFuncAttributeMaxDynamicSharedMemorySize, 69120);
    cudaFuncSetAttribute(k5, cudaFuncAttributeMaxDynamicSharedMemorySize, 64512);

    k1<<<dim3(25, 32), 256, 69120>>>(x, W1, b1, W2, b2, mt, Wd, bd);
    k2<<<256, 128>>>();
    k3a<<<dim3(8, 32), 256>>>();
    k4<<<144, 256>>>(Wh, bh);
    k5<<<dim3(14, 32), 256, 64512>>>(x, Wu, bu, out);
}